// round 1
// baseline (speedup 1.0000x reference)
#include <cuda_runtime.h>

#define NB 8
#define NS 1024
#define ND 128
#define NROWS (NB*NS)   // 8192
#define BSD (NB*NS*ND)  // 1048576

// ---- scratch (static device globals; no runtime allocation) ----
__device__ float g_k[NROWS*ND];
__device__ float g_v[NROWS*ND];
__device__ float g_q[NROWS*ND];
__device__ float g_err[NROWS*ND];
__device__ float g_gates[NROWS*3];   // [b][t][{a,e,theta}]
__device__ float g_A[NROWS];         // weight for M_final
__device__ float g_B[NROWS];         // weight for S_final
__device__ float g_part[NB*2*8*ND*ND]; // split-K partials [b][which][split][128][128]

// ============================================================
// Kernel 1: k = x@Wk, v = x@Wv, q = x@Wq   (8192x128 @ 128x128)
// Tiled SGEMM: block computes 128x128 tile, 256 thr, 8x8 per thread
// ============================================================
__global__ __launch_bounds__(256) void gemm_qkv_kernel(
    const float* __restrict__ x, const float* __restrict__ Wk,
    const float* __restrict__ Wv, const float* __restrict__ Wq)
{
    const int which = blockIdx.y;
    const float* __restrict__ W = (which == 0) ? Wk : ((which == 1) ? Wv : Wq);
    float* __restrict__ out = (which == 0) ? g_k : ((which == 1) ? g_v : g_q);
    const int rowBase = blockIdx.x * 128;

    __shared__ float Xs[16][128];  // [k][m]
    __shared__ float Ws[16][128];  // [k][n]

    const int tid = threadIdx.x;
    const int tx = tid & 15, ty = tid >> 4;

    float acc[8][8];
    #pragma unroll
    for (int i = 0; i < 8; i++)
        #pragma unroll
        for (int j = 0; j < 8; j++) acc[i][j] = 0.f;

    for (int k0 = 0; k0 < 128; k0 += 16) {
        #pragma unroll
        for (int i = 0; i < 2; i++) {
            int e4 = (tid + i*256) * 4;       // element in 2048-elem tile
            int m  = e4 >> 4, kk = e4 & 15;   // X tile: 128 rows x 16 k
            float4 xv = *reinterpret_cast<const float4*>(&x[(rowBase + m)*ND + k0 + kk]);
            Xs[kk+0][m] = xv.x; Xs[kk+1][m] = xv.y; Xs[kk+2][m] = xv.z; Xs[kk+3][m] = xv.w;
            int kw = e4 >> 7, n = e4 & 127;   // W tile: 16 k x 128 n
            float4 wv = *reinterpret_cast<const float4*>(&W[(k0 + kw)*ND + n]);
            *reinterpret_cast<float4*>(&Ws[kw][n]) = wv;
        }
        __syncthreads();
        #pragma unroll
        for (int kk = 0; kk < 16; kk++) {
            float afr[8], bfr[8];
            *reinterpret_cast<float4*>(&afr[0]) = *reinterpret_cast<const float4*>(&Xs[kk][ty*8]);
            *reinterpret_cast<float4*>(&afr[4]) = *reinterpret_cast<const float4*>(&Xs[kk][ty*8+4]);
            *reinterpret_cast<float4*>(&bfr[0]) = *reinterpret_cast<const float4*>(&Ws[kk][tx*8]);
            *reinterpret_cast<float4*>(&bfr[4]) = *reinterpret_cast<const float4*>(&Ws[kk][tx*8+4]);
            #pragma unroll
            for (int i = 0; i < 8; i++)
                #pragma unroll
                for (int j = 0; j < 8; j++)
                    acc[i][j] = fmaf(afr[i], bfr[j], acc[i][j]);
        }
        __syncthreads();
    }
    #pragma unroll
    for (int i = 0; i < 8; i++) {
        int m = rowBase + ty*8 + i;
        #pragma unroll
        for (int j = 0; j < 8; j += 4) {
            *reinterpret_cast<float4*>(&out[m*ND + tx*8 + j]) =
                make_float4(acc[i][j], acc[i][j+1], acc[i][j+2], acc[i][j+3]);
        }
    }
}

// ============================================================
// Kernel 2: gates = sigmoid(x@Wg + bg), one warp per row
// ============================================================
__global__ __launch_bounds__(128) void gates_kernel(
    const float* __restrict__ x, const float* __restrict__ Wg,
    const float* __restrict__ bg)
{
    const int warp = (blockIdx.x * 128 + threadIdx.x) >> 5;
    const int lane = threadIdx.x & 31;
    const float* __restrict__ xr = x + warp * ND;
    float x0 = xr[lane], x1 = xr[lane+32], x2 = xr[lane+64], x3 = xr[lane+96];
    #pragma unroll
    for (int g = 0; g < 3; g++) {
        float s = x0*Wg[lane*3+g] + x1*Wg[(lane+32)*3+g]
                + x2*Wg[(lane+64)*3+g] + x3*Wg[(lane+96)*3+g];
        #pragma unroll
        for (int o = 16; o; o >>= 1) s += __shfl_xor_sync(0xffffffffu, s, o);
        if (lane == 0) {
            float z = s + bg[g];
            g_gates[warp*3 + g] = 1.f / (1.f + expf(-z));
        }
    }
}

// ============================================================
// Kernel 3: per-batch diagonal scan (blocks 0..7) +
//           backward gate-weight scan (blocks 8..15)
// diag recurrence (per dim i, closed form of reference diag):
//   err  = k*dm - v
//   ds'  = e*ds - th*k*err = d0*dm + e*ds + c2   (d0=-th*k^2, c2=th*k*v)
//   dm'  = (1-a)*dm + ds'  = (d0+(1-a))*dm + e*ds + c2
// weights: P_t=prod_{u>t}(1-a_u), E_t=prod_{u>t}e_u,
//          w_t = P_t + e_{t+1} w_{t+1};  A_t=-th_t*w_t, B_t=-th_t*E_t
// ============================================================
__global__ __launch_bounds__(128) void scan_kernel(float* __restrict__ d_out)
{
    const int b = blockIdx.x;
    if (b < NB) {
        const int i = threadIdx.x;
        const float* __restrict__ kp = g_k + b*NS*ND;
        const float* __restrict__ vp = g_v + b*NS*ND;
        const float* __restrict__ qp = g_q + b*NS*ND;
        float* __restrict__ ep = g_err + b*NS*ND;
        float* __restrict__ op = d_out + b*NS*ND;
        const float* __restrict__ gp = g_gates + b*NS*3;
        float dm = 0.f, ds = 0.f;
        #pragma unroll 4
        for (int t = 0; t < NS; t++) {
            const int idx = t*ND + i;
            const float a  = gp[3*t+0];
            const float e  = gp[3*t+1];
            const float th = gp[3*t+2];
            const float kk = kp[idx];
            const float vv = vp[idx];
            const float qq = qp[idx];
            op[idx] = qq * dm;
            const float err = fmaf(kk, dm, -vv);
            ep[idx] = err;
            const float thk = th * kk;
            const float c2  = thk * vv;
            const float d0  = -thk * kk;
            const float c0  = d0 + (1.f - a);
            const float inner = fmaf(e, ds, c2);  // off dm-chain
            const float dmn = fmaf(c0, dm, inner);
            ds = fmaf(d0, dm, inner);
            dm = dmn;
        }
    } else {
        const int b2 = b - NB;
        __shared__ float sg[128][3];
        __shared__ float sA[128];
        __shared__ float sB[128];
        __shared__ float carry[3];
        if (threadIdx.x == 0) { carry[0] = 1.f; carry[1] = 1.f; carry[2] = 1.f; }
        const float* __restrict__ gp = g_gates + b2*NS*3;
        for (int c = 7; c >= 0; c--) {
            const int t = c*128 + threadIdx.x;
            sg[threadIdx.x][0] = gp[3*t+0];
            sg[threadIdx.x][1] = gp[3*t+1];
            sg[threadIdx.x][2] = gp[3*t+2];
            __syncthreads();
            if (threadIdx.x == 0) {
                float P = carry[0], E = carry[1], w = carry[2];
                for (int j = 127; j >= 0; j--) {
                    const float a = sg[j][0], e = sg[j][1], th = sg[j][2];
                    sA[j] = -th * w;
                    sB[j] = -th * E;
                    P *= (1.f - a);           // P_{t-1}
                    E *= e;                   // E_{t-1}
                    w  = fmaf(e, w, P);       // w_{t-1} = P_{t-1} + e_t*w_t
                }
                carry[0] = P; carry[1] = E; carry[2] = w;
            }
            __syncthreads();
            g_A[b2*NS + t] = sA[threadIdx.x];
            g_B[b2*NS + t] = sB[threadIdx.x];
            __syncthreads();
        }
    }
}

// ============================================================
// Kernel 4: split-K weighted outer-product GEMMs ->
//   C[b,which][i][j] = sum_t wgt_t * k[b,t,i] * err[b,t,j]
// 128 blocks: (b, which in {M,S}, split in [0,8)); partials to g_part
// ============================================================
__global__ __launch_bounds__(256) void final_gemm_kernel()
{
    const int split = blockIdx.x & 7;
    const int which = (blockIdx.x >> 3) & 1;
    const int b     = blockIdx.x >> 4;
    const float* __restrict__ kp = g_k   + b*NS*ND;
    const float* __restrict__ ep = g_err + b*NS*ND;
    const float* __restrict__ wp = ((which == 0) ? g_A : g_B) + b*NS;
    float* __restrict__ C = g_part + ((b*2 + which)*8 + split)*ND*ND;
    const int t0 = split * 128;

    __shared__ float Ks[16][128];  // [t][i] weighted
    __shared__ float Es[16][128];  // [t][j]

    const int tid = threadIdx.x;
    const int tx = tid & 15, ty = tid >> 4;

    float acc[8][8];
    #pragma unroll
    for (int i = 0; i < 8; i++)
        #pragma unroll
        for (int j = 0; j < 8; j++) acc[i][j] = 0.f;

    for (int k0 = 0; k0 < 128; k0 += 16) {
        #pragma unroll
        for (int i = 0; i < 2; i++) {
            int e4 = (tid + i*256) * 4;
            int kk = e4 >> 7, n = e4 & 127;
            int t  = t0 + k0 + kk;
            float wgt = wp[t];
            float4 kv = *reinterpret_cast<const float4*>(&kp[t*ND + n]);
            Ks[kk][n+0] = wgt*kv.x; Ks[kk][n+1] = wgt*kv.y;
            Ks[kk][n+2] = wgt*kv.z; Ks[kk][n+3] = wgt*kv.w;
            float4 ev = *reinterpret_cast<const float4*>(&ep[t*ND + n]);
            *reinterpret_cast<float4*>(&Es[kk][n]) = ev;
        }
        __syncthreads();
        #pragma unroll
        for (int kk = 0; kk < 16; kk++) {
            float afr[8], bfr[8];
            *reinterpret_cast<float4*>(&afr[0]) = *reinterpret_cast<const float4*>(&Ks[kk][ty*8]);
            *reinterpret_cast<float4*>(&afr[4]) = *reinterpret_cast<const float4*>(&Ks[kk][ty*8+4]);
            *reinterpret_cast<float4*>(&bfr[0]) = *reinterpret_cast<const float4*>(&Es[kk][tx*8]);
            *reinterpret_cast<float4*>(&bfr[4]) = *reinterpret_cast<const float4*>(&Es[kk][tx*8+4]);
            #pragma unroll
            for (int i = 0; i < 8; i++)
                #pragma unroll
                for (int j = 0; j < 8; j++)
                    acc[i][j] = fmaf(afr[i], bfr[j], acc[i][j]);
        }
        __syncthreads();
    }
    #pragma unroll
    for (int i = 0; i < 8; i++) {
        #pragma unroll
        for (int j = 0; j < 8; j += 4) {
            *reinterpret_cast<float4*>(&C[(ty*8+i)*ND + tx*8 + j]) =
                make_float4(acc[i][j], acc[i][j+1], acc[i][j+2], acc[i][j+3]);
        }
    }
}

// ============================================================
// Kernel 5: reduce split-K partials into d_out (deterministic)
// d_out layout: [outputs(8,1024,128)][M_final(8,128,128)][S_final(8,128,128)]
// ============================================================
__global__ __launch_bounds__(256) void reduce_kernel(float* __restrict__ d_out)
{
    const int gid = blockIdx.x * 256 + threadIdx.x;  // [0, 262144)
    const int which = gid >> 17;
    const int r  = gid & 131071;
    const int b  = r >> 14;
    const int ij = r & 16383;
    const float* __restrict__ p = g_part + ((b*2 + which)*8)*ND*ND + ij;
    float s = 0.f;
    #pragma unroll
    for (int sp = 0; sp < 8; sp++) s += p[sp*ND*ND];
    d_out[BSD + gid] = s;
}

// ============================================================
extern "C" void kernel_launch(void* const* d_in, const int* in_sizes, int n_in,
                              void* d_out, int out_size)
{
    const float* x  = (const float*)d_in[0];
    const float* Wk = (const float*)d_in[1];
    const float* Wv = (const float*)d_in[2];
    const float* Wq = (const float*)d_in[3];
    const float* Wg = (const float*)d_in[4];
    const float* bg = (const float*)d_in[5];
    float* out = (float*)d_out;

    gemm_qkv_kernel<<<dim3(64, 3), 256>>>(x, Wk, Wv, Wq);
    gates_kernel<<<2048, 128>>>(x, Wg, bg);
    scan_kernel<<<16, 128>>>(out);
    final_gemm_kernel<<<128, 256>>>();
    reduce_kernel<<<1024, 256>>>(out);
}

// round 2
// speedup vs baseline: 3.8924x; 3.8924x over previous
#include <cuda_runtime.h>

#define NB 8
#define NS 1024
#define ND 128
#define NROWS (NB*NS)   // 8192
#define BSD (NB*NS*ND)  // 1048576

#define NC 16           // diag chunks
#define LC 64           // steps per diag chunk
#define UG 8            // prefetch group size
#define NGRP (LC/UG)    // 8 groups per chunk

#define NWC 32          // weight chunks
#define LW 32           // steps per weight chunk
#define NSPLIT 16       // final gemm K-splits

// ---- scratch (static device globals; no runtime allocation) ----
__device__ float  g_k[NROWS*ND];
__device__ float  g_v[NROWS*ND];
__device__ float  g_q[NROWS*ND];
__device__ float  g_err[NROWS*ND];
__device__ float4 g_g4[NROWS];           // (om=1-a, e, th, 0) per (b,t)
__device__ float  g_A[NROWS];            // weight for M_final
__device__ float  g_B[NROWS];            // weight for S_final
__device__ float  g_dmap[6*NB*NC*ND];    // composed diag maps: m00,m01,m10,m11,v0,v1
__device__ float  g_dinit0[NB*NC*ND];    // dm at chunk entry
__device__ float  g_dinit1[NB*NC*ND];    // ds at chunk entry
__device__ float  g_wmap[3*NB*NWC];      // composed weight maps: p^, q^, gamma^
__device__ float  g_winit[NB*NWC*3];     // (P,E,w) at chunk entry (backward order)
__device__ float  g_part[NB*2*NSPLIT*ND*ND]; // split-K partials

// ============================================================
// Kernel 1: k = x@Wk, v = x@Wv, q = x@Wq   (8192x128 @ 128x128)
// ============================================================
__global__ __launch_bounds__(256) void gemm_qkv_kernel(
    const float* __restrict__ x, const float* __restrict__ Wk,
    const float* __restrict__ Wv, const float* __restrict__ Wq)
{
    const int which = blockIdx.y;
    const float* __restrict__ W = (which == 0) ? Wk : ((which == 1) ? Wv : Wq);
    float* __restrict__ out = (which == 0) ? g_k : ((which == 1) ? g_v : g_q);
    const int rowBase = blockIdx.x * 128;

    __shared__ float Xs[16][128];
    __shared__ float Ws[16][128];

    const int tid = threadIdx.x;
    const int tx = tid & 15, ty = tid >> 4;

    float acc[8][8];
    #pragma unroll
    for (int i = 0; i < 8; i++)
        #pragma unroll
        for (int j = 0; j < 8; j++) acc[i][j] = 0.f;

    for (int k0 = 0; k0 < 128; k0 += 16) {
        #pragma unroll
        for (int i = 0; i < 2; i++) {
            int e4 = (tid + i*256) * 4;
            int m  = e4 >> 4, kk = e4 & 15;
            float4 xv = *reinterpret_cast<const float4*>(&x[(rowBase + m)*ND + k0 + kk]);
            Xs[kk+0][m] = xv.x; Xs[kk+1][m] = xv.y; Xs[kk+2][m] = xv.z; Xs[kk+3][m] = xv.w;
            int kw = e4 >> 7, n = e4 & 127;
            float4 wv = *reinterpret_cast<const float4*>(&W[(k0 + kw)*ND + n]);
            *reinterpret_cast<float4*>(&Ws[kw][n]) = wv;
        }
        __syncthreads();
        #pragma unroll
        for (int kk = 0; kk < 16; kk++) {
            float afr[8], bfr[8];
            *reinterpret_cast<float4*>(&afr[0]) = *reinterpret_cast<const float4*>(&Xs[kk][ty*8]);
            *reinterpret_cast<float4*>(&afr[4]) = *reinterpret_cast<const float4*>(&Xs[kk][ty*8+4]);
            *reinterpret_cast<float4*>(&bfr[0]) = *reinterpret_cast<const float4*>(&Ws[kk][tx*8]);
            *reinterpret_cast<float4*>(&bfr[4]) = *reinterpret_cast<const float4*>(&Ws[kk][tx*8+4]);
            #pragma unroll
            for (int i = 0; i < 8; i++)
                #pragma unroll
                for (int j = 0; j < 8; j++)
                    acc[i][j] = fmaf(afr[i], bfr[j], acc[i][j]);
        }
        __syncthreads();
    }
    #pragma unroll
    for (int i = 0; i < 8; i++) {
        int m = rowBase + ty*8 + i;
        #pragma unroll
        for (int j = 0; j < 8; j += 4) {
            *reinterpret_cast<float4*>(&out[m*ND + tx*8 + j]) =
                make_float4(acc[i][j], acc[i][j+1], acc[i][j+2], acc[i][j+3]);
        }
    }
}

// ============================================================
// Kernel 2: gates -> g_g4[t] = (1-sigmoid(z0), sigmoid(z1), sigmoid(z2), 0)
// one warp per row
// ============================================================
__global__ __launch_bounds__(128) void gates_kernel(
    const float* __restrict__ x, const float* __restrict__ Wg,
    const float* __restrict__ bg)
{
    const int warp = (blockIdx.x * 128 + threadIdx.x) >> 5;
    const int lane = threadIdx.x & 31;
    const float* __restrict__ xr = x + warp * ND;
    float x0 = xr[lane], x1 = xr[lane+32], x2 = xr[lane+64], x3 = xr[lane+96];
    float z[3];
    #pragma unroll
    for (int g = 0; g < 3; g++) {
        float s = x0*Wg[lane*3+g] + x1*Wg[(lane+32)*3+g]
                + x2*Wg[(lane+64)*3+g] + x3*Wg[(lane+96)*3+g];
        #pragma unroll
        for (int o = 16; o; o >>= 1) s += __shfl_xor_sync(0xffffffffu, s, o);
        z[g] = s + bg[g];
    }
    if (lane == 0) {
        float om = 1.f / (1.f + expf(z[0]));      // 1 - sigmoid(z0)
        float e  = 1.f / (1.f + expf(-z[1]));
        float th = 1.f / (1.f + expf(-z[2]));
        g_g4[warp] = make_float4(om, e, th, 0.f);
    }
}

// ============================================================
// Pass 1: chunk map composition
//  diag step map: A_t = [[om+d0, e],[d0, e]], b_t = (c2, c2)
//    with t1=th*k, c2=t1*v, d0=-t1*k
//  weight step map (processed in DESCENDING t):
//    (P,E,w) <- (p*P, q*E, q*w + p*P),  p=om, q=e
// ============================================================
__global__ __launch_bounds__(128) void pass1_kernel()
{
    const int blk = blockIdx.x;
    if (blk < NB*NC) {
        const int b = blk >> 4, c = blk & (NC-1);
        const int i = threadIdx.x;
        const int t0 = c * LC;
        const float*  __restrict__ kp = g_k + (b*NS + t0)*ND + i;
        const float*  __restrict__ vp = g_v + (b*NS + t0)*ND + i;
        const float4* __restrict__ gp = g_g4 + b*NS + t0;

        float m00=1.f, m01=0.f, m10=0.f, m11=1.f, w0=0.f, w1=0.f;
        float kA[UG], vA[UG], kB[UG], vB[UG];
        float4 gA[UG], gB[UG];
        #pragma unroll
        for (int s = 0; s < UG; s++) { kA[s]=kp[s*ND]; vA[s]=vp[s*ND]; gA[s]=gp[s]; }

        #pragma unroll
        for (int g = 0; g < NGRP; g++) {
            const bool useA = ((g & 1) == 0);
            if (g + 1 < NGRP) {
                #pragma unroll
                for (int s = 0; s < UG; s++) {
                    int off = ((g+1)*UG + s)*ND;
                    int go  = (g+1)*UG + s;
                    if (useA) { kB[s]=kp[off]; vB[s]=vp[off]; gB[s]=gp[go]; }
                    else      { kA[s]=kp[off]; vA[s]=vp[off]; gA[s]=gp[go]; }
                }
            }
            #pragma unroll
            for (int s = 0; s < UG; s++) {
                float  kk = useA ? kA[s] : kB[s];
                float  vv = useA ? vA[s] : vB[s];
                float4 gg = useA ? gA[s] : gB[s];
                float om = gg.x, e = gg.y, th = gg.z;
                float t1 = th*kk, c2 = t1*vv, d0 = -t1*kk, a00 = om + d0;
                float te0 = e*m10, te1 = e*m11;
                float n00 = fmaf(a00, m00, te0), n10 = fmaf(d0, m00, te0);
                float n01 = fmaf(a00, m01, te1), n11 = fmaf(d0, m01, te1);
                float tev = fmaf(e, w1, c2);
                float nw0 = fmaf(a00, w0, tev), nw1 = fmaf(d0, w0, tev);
                m00=n00; m01=n01; m10=n10; m11=n11; w0=nw0; w1=nw1;
            }
        }
        const int base = (b*NC + c)*ND + i;
        const int ST = NB*NC*ND;
        g_dmap[0*ST+base] = m00; g_dmap[1*ST+base] = m01;
        g_dmap[2*ST+base] = m10; g_dmap[3*ST+base] = m11;
        g_dmap[4*ST+base] = w0;  g_dmap[5*ST+base] = w1;
    } else {
        const int u = (blk - NB*NC)*128 + threadIdx.x;   // (b, wc)
        if (u < NB*NWC) {
            const int b = u >> 5, wc = u & (NWC-1);
            const float4* __restrict__ gp = g_g4 + b*NS + wc*LW;
            float ph = 1.f, qh = 1.f, gh = 0.f;
            #pragma unroll 4
            for (int s = LW-1; s >= 0; s--) {
                float4 g = gp[s];
                float p = g.x, q = g.y;
                gh = fmaf(q, gh, p*ph);   // uses old ph
                ph *= p;
                qh *= q;
            }
            g_wmap[0*NB*NWC + u] = ph;
            g_wmap[1*NB*NWC + u] = qh;
            g_wmap[2*NB*NWC + u] = gh;
        }
    }
}

// ============================================================
// Pass 2: sequential combine over chunk maps -> chunk-entry states
// ============================================================
__global__ __launch_bounds__(128) void pass2_kernel()
{
    if (blockIdx.x < NB) {
        const int b = blockIdx.x, d = threadIdx.x;
        const int ST = NB*NC*ND;
        float s0 = 0.f, s1 = 0.f;
        #pragma unroll
        for (int c = 0; c < NC; c++) {
            const int idx = (b*NC + c)*ND + d;
            g_dinit0[idx] = s0; g_dinit1[idx] = s1;
            float m00 = g_dmap[0*ST+idx], m01 = g_dmap[1*ST+idx];
            float m10 = g_dmap[2*ST+idx], m11 = g_dmap[3*ST+idx];
            float v0  = g_dmap[4*ST+idx], v1  = g_dmap[5*ST+idx];
            float ns0 = fmaf(m00, s0, fmaf(m01, s1, v0));
            float ns1 = fmaf(m10, s0, fmaf(m11, s1, v1));
            s0 = ns0; s1 = ns1;
        }
    } else if (threadIdx.x < NB) {
        const int b = threadIdx.x;
        float P = 1.f, E = 1.f, w = 1.f;
        #pragma unroll
        for (int wc = NWC-1; wc >= 0; wc--) {
            const int u = b*NWC + wc;
            g_winit[u*3+0] = P; g_winit[u*3+1] = E; g_winit[u*3+2] = w;
            float ph = g_wmap[0*NB*NWC + u];
            float qh = g_wmap[1*NB*NWC + u];
            float gh = g_wmap[2*NB*NWC + u];
            float nw = fmaf(qh, w, gh*P);
            P *= ph; E *= qh; w = nw;
        }
    }
}

// ============================================================
// Pass 3: replay within chunks, emitting y (d_out), err, A_t, B_t
// ============================================================
__global__ __launch_bounds__(128) void pass3_kernel(float* __restrict__ d_out)
{
    const int blk = blockIdx.x;
    if (blk < NB*NC) {
        const int b = blk >> 4, c = blk & (NC-1);
        const int i = threadIdx.x;
        const int t0 = c * LC;
        const float*  __restrict__ kp = g_k + (b*NS + t0)*ND + i;
        const float*  __restrict__ vp = g_v + (b*NS + t0)*ND + i;
        const float*  __restrict__ qp = g_q + (b*NS + t0)*ND + i;
        const float4* __restrict__ gp = g_g4 + b*NS + t0;
        float* __restrict__ op = d_out + (b*NS + t0)*ND + i;
        float* __restrict__ ep = g_err + (b*NS + t0)*ND + i;

        const int ii = (b*NC + c)*ND + i;
        float dm = g_dinit0[ii], ds = g_dinit1[ii];

        float kA[UG], vA[UG], qA[UG], kB[UG], vB[UG], qB[UG];
        float4 gA[UG], gB[UG];
        #pragma unroll
        for (int s = 0; s < UG; s++) { kA[s]=kp[s*ND]; vA[s]=vp[s*ND]; qA[s]=qp[s*ND]; gA[s]=gp[s]; }

        #pragma unroll
        for (int g = 0; g < NGRP; g++) {
            const bool useA = ((g & 1) == 0);
            if (g + 1 < NGRP) {
                #pragma unroll
                for (int s = 0; s < UG; s++) {
                    int off = ((g+1)*UG + s)*ND;
                    int go  = (g+1)*UG + s;
                    if (useA) { kB[s]=kp[off]; vB[s]=vp[off]; qB[s]=qp[off]; gB[s]=gp[go]; }
                    else      { kA[s]=kp[off]; vA[s]=vp[off]; qA[s]=qp[off]; gA[s]=gp[go]; }
                }
            }
            #pragma unroll
            for (int s = 0; s < UG; s++) {
                float  kk = useA ? kA[s] : kB[s];
                float  vv = useA ? vA[s] : vB[s];
                float  qq = useA ? qA[s] : qB[s];
                float4 gg = useA ? gA[s] : gB[s];
                float om = gg.x, e = gg.y, th = gg.z;
                const int off = (g*UG + s)*ND;
                op[off] = qq * dm;                    // y_t = q_t * dm_{t-1}
                float err = fmaf(kk, dm, -vv);
                ep[off] = err;
                float t1 = th*kk, c2 = t1*vv, d0 = -t1*kk;
                float inner = fmaf(e, ds, c2);
                ds = fmaf(d0, dm, inner);             // S diag update
                dm = fmaf(om, dm, ds);                // M diag update
            }
        }
    } else {
        const int u = (blk - NB*NC)*128 + threadIdx.x;
        if (u < NB*NWC) {
            const int b = u >> 5, wc = u & (NWC-1);
            const float4* __restrict__ gp = g_g4 + b*NS + wc*LW;
            float P = g_winit[u*3+0], E = g_winit[u*3+1], w = g_winit[u*3+2];
            #pragma unroll 4
            for (int s = LW-1; s >= 0; s--) {
                float4 g = gp[s];
                float th = g.z;
                g_A[b*NS + wc*LW + s] = -th * w;
                g_B[b*NS + wc*LW + s] = -th * E;
                P *= g.x;
                E *= g.y;
                w  = fmaf(g.y, w, P);   // uses updated P
            }
        }
    }
}

// ============================================================
// Kernel 4: split-K weighted outer-product GEMMs
//   C[b,which][i][j] = sum_t wgt_t * k[b,t,i] * err[b,t,j]
// grid = NB * 2 * NSPLIT blocks, 64 steps per split
// ============================================================
__global__ __launch_bounds__(256) void final_gemm_kernel()
{
    const int split = blockIdx.x & (NSPLIT-1);
    const int which = (blockIdx.x >> 4) & 1;
    const int b     = blockIdx.x >> 5;
    const float* __restrict__ kp = g_k   + b*NS*ND;
    const float* __restrict__ ep = g_err + b*NS*ND;
    const float* __restrict__ wp = ((which == 0) ? g_A : g_B) + b*NS;
    float* __restrict__ C = g_part + ((b*2 + which)*NSPLIT + split)*ND*ND;
    const int t0 = split * (NS/NSPLIT);   // 64 steps

    __shared__ float Ks[16][128];
    __shared__ float Es[16][128];

    const int tid = threadIdx.x;
    const int tx = tid & 15, ty = tid >> 4;

    float acc[8][8];
    #pragma unroll
    for (int i = 0; i < 8; i++)
        #pragma unroll
        for (int j = 0; j < 8; j++) acc[i][j] = 0.f;

    for (int k0 = 0; k0 < NS/NSPLIT; k0 += 16) {
        #pragma unroll
        for (int i = 0; i < 2; i++) {
            int e4 = (tid + i*256) * 4;
            int kk = e4 >> 7, n = e4 & 127;
            int t  = t0 + k0 + kk;
            float wgt = wp[t];
            float4 kv = *reinterpret_cast<const float4*>(&kp[t*ND + n]);
            Ks[kk][n+0] = wgt*kv.x; Ks[kk][n+1] = wgt*kv.y;
            Ks[kk][n+2] = wgt*kv.z; Ks[kk][n+3] = wgt*kv.w;
            float4 ev = *reinterpret_cast<const float4*>(&ep[t*ND + n]);
            *reinterpret_cast<float4*>(&Es[kk][n]) = ev;
        }
        __syncthreads();
        #pragma unroll
        for (int kk = 0; kk < 16; kk++) {
            float afr[8], bfr[8];
            *reinterpret_cast<float4*>(&afr[0]) = *reinterpret_cast<const float4*>(&Ks[kk][ty*8]);
            *reinterpret_cast<float4*>(&afr[4]) = *reinterpret_cast<const float4*>(&Ks[kk][ty*8+4]);
            *reinterpret_cast<float4*>(&bfr[0]) = *reinterpret_cast<const float4*>(&Es[kk][tx*8]);
            *reinterpret_cast<float4*>(&bfr[4]) = *reinterpret_cast<const float4*>(&Es[kk][tx*8+4]);
            #pragma unroll
            for (int i = 0; i < 8; i++)
                #pragma unroll
                for (int j = 0; j < 8; j++)
                    acc[i][j] = fmaf(afr[i], bfr[j], acc[i][j]);
        }
        __syncthreads();
    }
    #pragma unroll
    for (int i = 0; i < 8; i++) {
        #pragma unroll
        for (int j = 0; j < 8; j += 4) {
            *reinterpret_cast<float4*>(&C[(ty*8+i)*ND + tx*8 + j]) =
                make_float4(acc[i][j], acc[i][j+1], acc[i][j+2], acc[i][j+3]);
        }
    }
}

// ============================================================
// Kernel 5: reduce split-K partials -> d_out tail
// d_out layout: [outputs(8,1024,128)][M_final(8,128,128)][S_final(8,128,128)]
// ============================================================
__global__ __launch_bounds__(256) void reduce_kernel(float* __restrict__ d_out)
{
    const int gid = blockIdx.x * 256 + threadIdx.x;  // [0, 262144)
    const int which = gid >> 17;
    const int r  = gid & 131071;
    const int b  = r >> 14;
    const int ij = r & 16383;
    const float* __restrict__ p = g_part + ((b*2 + which)*NSPLIT)*ND*ND + ij;
    float s = 0.f;
    #pragma unroll
    for (int sp = 0; sp < NSPLIT; sp++) s += p[sp*ND*ND];
    d_out[BSD + gid] = s;
}

// ============================================================
extern "C" void kernel_launch(void* const* d_in, const int* in_sizes, int n_in,
                              void* d_out, int out_size)
{
    const float* x  = (const float*)d_in[0];
    const float* Wk = (const float*)d_in[1];
    const float* Wv = (const float*)d_in[2];
    const float* Wq = (const float*)d_in[3];
    const float* Wg = (const float*)d_in[4];
    const float* bg = (const float*)d_in[5];
    float* out = (float*)d_out;

    gemm_qkv_kernel<<<dim3(64, 3), 256>>>(x, Wk, Wv, Wq);
    gates_kernel<<<2048, 128>>>(x, Wg, bg);
    pass1_kernel<<<NB*NC + 2, 128>>>();
    pass2_kernel<<<NB + 1, 128>>>();
    pass3_kernel<<<NB*NC + 2, 128>>>(out);
    final_gemm_kernel<<<NB*2*NSPLIT, 256>>>();
    reduce_kernel<<<1024, 256>>>(out);
}

// round 3
// speedup vs baseline: 4.6172x; 1.1862x over previous
#include <cuda_runtime.h>

#define NB 8
#define NS 1024
#define ND 128
#define NROWS (NB*NS)   // 8192
#define BSD (NB*NS*ND)  // 1048576

#define NC 16           // chunks (shared by diag scan and final gemm splits)
#define LC 64           // steps per chunk
#define UG 8            // prefetch group size
#define NGRP (LC/UG)

// ---- scratch (static device globals; no runtime allocation) ----
__device__ float  g_k[NROWS*ND];
__device__ float  g_v[NROWS*ND];
__device__ float  g_q[NROWS*ND];
__device__ float4 g_g4[NROWS];           // (om=1-a, e, th, 0) per (b,t)
__device__ float  g_dmap[6*NB*NC*ND];    // composed diag maps: m00,m01,m10,m11,v0,v1
__device__ float  g_dinit0[NB*NC*ND];    // dm at chunk entry
__device__ float  g_dinit1[NB*NC*ND];    // ds at chunk entry
__device__ float  g_wmap[3*NB*NC];       // composed weight maps: p^, q^, gamma^
__device__ float  g_winit[NB*NC*3];      // (P,E,w) at chunk entry (backward order)
__device__ float  g_part[NB*2*NC*ND*ND]; // split-K partials

// ============================================================
// Kernel 1: y<3: k/v/q = x@W  (8192x128 @ 128x128), y==3: gates
// ============================================================
__global__ __launch_bounds__(256) void k1_qkv_gates(
    const float* __restrict__ x, const float* __restrict__ Wk,
    const float* __restrict__ Wv, const float* __restrict__ Wq,
    const float* __restrict__ Wg, const float* __restrict__ bg)
{
    const int which = blockIdx.y;
    if (which == 3) {
        // gates: 64 blocks x 128 rows each; warp-per-row, 16 rows/warp
        const int base = blockIdx.x * 128;
        const int w = threadIdx.x >> 5, lane = threadIdx.x & 31;
        const float b0 = bg[0], b1 = bg[1], b2 = bg[2];
        const float w0a = Wg[lane*3+0],      w0b = Wg[lane*3+1],      w0c = Wg[lane*3+2];
        const float w1a = Wg[(lane+32)*3+0], w1b = Wg[(lane+32)*3+1], w1c = Wg[(lane+32)*3+2];
        const float w2a = Wg[(lane+64)*3+0], w2b = Wg[(lane+64)*3+1], w2c = Wg[(lane+64)*3+2];
        const float w3a = Wg[(lane+96)*3+0], w3b = Wg[(lane+96)*3+1], w3c = Wg[(lane+96)*3+2];
        for (int rr = 0; rr < 16; rr++) {
            const int r = base + w*16 + rr;
            const float* __restrict__ xr = x + r * ND;
            float x0 = xr[lane], x1 = xr[lane+32], x2 = xr[lane+64], x3 = xr[lane+96];
            float s0 = x0*w0a + x1*w1a + x2*w2a + x3*w3a;
            float s1 = x0*w0b + x1*w1b + x2*w2b + x3*w3b;
            float s2 = x0*w0c + x1*w1c + x2*w2c + x3*w3c;
            #pragma unroll
            for (int o = 16; o; o >>= 1) {
                s0 += __shfl_xor_sync(0xffffffffu, s0, o);
                s1 += __shfl_xor_sync(0xffffffffu, s1, o);
                s2 += __shfl_xor_sync(0xffffffffu, s2, o);
            }
            if (lane == 0) {
                float om = 1.f / (1.f + expf(s0 + b0));       // 1 - sigmoid
                float e  = 1.f / (1.f + expf(-(s1 + b1)));
                float th = 1.f / (1.f + expf(-(s2 + b2)));
                g_g4[r] = make_float4(om, e, th, 0.f);
            }
        }
        return;
    }
    const float* __restrict__ W = (which == 0) ? Wk : ((which == 1) ? Wv : Wq);
    float* __restrict__ out = (which == 0) ? g_k : ((which == 1) ? g_v : g_q);
    const int rowBase = blockIdx.x * 128;

    __shared__ float Xs[16][128];
    __shared__ float Ws[16][128];

    const int tid = threadIdx.x;
    const int tx = tid & 15, ty = tid >> 4;

    float acc[8][8];
    #pragma unroll
    for (int i = 0; i < 8; i++)
        #pragma unroll
        for (int j = 0; j < 8; j++) acc[i][j] = 0.f;

    for (int k0 = 0; k0 < 128; k0 += 16) {
        #pragma unroll
        for (int i = 0; i < 2; i++) {
            int e4 = (tid + i*256) * 4;
            int m  = e4 >> 4, kk = e4 & 15;
            float4 xv = *reinterpret_cast<const float4*>(&x[(rowBase + m)*ND + k0 + kk]);
            Xs[kk+0][m] = xv.x; Xs[kk+1][m] = xv.y; Xs[kk+2][m] = xv.z; Xs[kk+3][m] = xv.w;
            int kw = e4 >> 7, n = e4 & 127;
            float4 wv = *reinterpret_cast<const float4*>(&W[(k0 + kw)*ND + n]);
            *reinterpret_cast<float4*>(&Ws[kw][n]) = wv;
        }
        __syncthreads();
        #pragma unroll
        for (int kk = 0; kk < 16; kk++) {
            float afr[8], bfr[8];
            *reinterpret_cast<float4*>(&afr[0]) = *reinterpret_cast<const float4*>(&Xs[kk][ty*8]);
            *reinterpret_cast<float4*>(&afr[4]) = *reinterpret_cast<const float4*>(&Xs[kk][ty*8+4]);
            *reinterpret_cast<float4*>(&bfr[0]) = *reinterpret_cast<const float4*>(&Ws[kk][tx*8]);
            *reinterpret_cast<float4*>(&bfr[4]) = *reinterpret_cast<const float4*>(&Ws[kk][tx*8+4]);
            #pragma unroll
            for (int i = 0; i < 8; i++)
                #pragma unroll
                for (int j = 0; j < 8; j++)
                    acc[i][j] = fmaf(afr[i], bfr[j], acc[i][j]);
        }
        __syncthreads();
    }
    #pragma unroll
    for (int i = 0; i < 8; i++) {
        int m = rowBase + ty*8 + i;
        #pragma unroll
        for (int j = 0; j < 8; j += 4) {
            *reinterpret_cast<float4*>(&out[m*ND + tx*8 + j]) =
                make_float4(acc[i][j], acc[i][j+1], acc[i][j+2], acc[i][j+3]);
        }
    }
}

// ============================================================
// Pass 1: chunk map composition (diag maps + weight maps)
// ============================================================
__global__ __launch_bounds__(128) void pass1_kernel()
{
    const int blk = blockIdx.x;
    if (blk < NB*NC) {
        const int b = blk >> 4, c = blk & (NC-1);
        const int i = threadIdx.x;
        const int t0 = c * LC;
        const float*  __restrict__ kp = g_k + (b*NS + t0)*ND + i;
        const float*  __restrict__ vp = g_v + (b*NS + t0)*ND + i;
        const float4* __restrict__ gp = g_g4 + b*NS + t0;

        float m00=1.f, m01=0.f, m10=0.f, m11=1.f, w0=0.f, w1=0.f;
        float kA[UG], vA[UG], kB[UG], vB[UG];
        float4 gA[UG], gB[UG];
        #pragma unroll
        for (int s = 0; s < UG; s++) { kA[s]=kp[s*ND]; vA[s]=vp[s*ND]; gA[s]=gp[s]; }

        #pragma unroll
        for (int g = 0; g < NGRP; g++) {
            const bool useA = ((g & 1) == 0);
            if (g + 1 < NGRP) {
                #pragma unroll
                for (int s = 0; s < UG; s++) {
                    int off = ((g+1)*UG + s)*ND;
                    int go  = (g+1)*UG + s;
                    if (useA) { kB[s]=kp[off]; vB[s]=vp[off]; gB[s]=gp[go]; }
                    else      { kA[s]=kp[off]; vA[s]=vp[off]; gA[s]=gp[go]; }
                }
            }
            #pragma unroll
            for (int s = 0; s < UG; s++) {
                float  kk = useA ? kA[s] : kB[s];
                float  vv = useA ? vA[s] : vB[s];
                float4 gg = useA ? gA[s] : gB[s];
                float om = gg.x, e = gg.y, th = gg.z;
                float t1 = th*kk, c2 = t1*vv, d0 = -t1*kk, a00 = om + d0;
                float te0 = e*m10, te1 = e*m11;
                float n00 = fmaf(a00, m00, te0), n10 = fmaf(d0, m00, te0);
                float n01 = fmaf(a00, m01, te1), n11 = fmaf(d0, m01, te1);
                float tev = fmaf(e, w1, c2);
                float nw0 = fmaf(a00, w0, tev), nw1 = fmaf(d0, w0, tev);
                m00=n00; m01=n01; m10=n10; m11=n11; w0=nw0; w1=nw1;
            }
        }
        const int base = (b*NC + c)*ND + i;
        const int ST = NB*NC*ND;
        g_dmap[0*ST+base] = m00; g_dmap[1*ST+base] = m01;
        g_dmap[2*ST+base] = m10; g_dmap[3*ST+base] = m11;
        g_dmap[4*ST+base] = w0;  g_dmap[5*ST+base] = w1;
    } else {
        const int u = threadIdx.x;   // (b, wc), 128 units
        const int b = u >> 4, wc = u & (NC-1);
        const float4* __restrict__ gp = g_g4 + b*NS + wc*LC;
        float ph = 1.f, qh = 1.f, gh = 0.f;
        #pragma unroll 4
        for (int s = LC-1; s >= 0; s--) {
            float4 g = gp[s];
            float p = g.x, q = g.y;
            gh = fmaf(q, gh, p*ph);   // uses old ph
            ph *= p;
            qh *= q;
        }
        g_wmap[0*NB*NC + u] = ph;
        g_wmap[1*NB*NC + u] = qh;
        g_wmap[2*NB*NC + u] = gh;
    }
}

// ============================================================
// Pass 2: sequential combine over chunk maps -> chunk-entry states
// All loads prefetched up-front (MLP ~96) to avoid serialized round-trips
// ============================================================
__global__ __launch_bounds__(128) void pass2_kernel()
{
    if (blockIdx.x < NB) {
        const int b = blockIdx.x, d = threadIdx.x;
        const int ST = NB*NC*ND;
        float pm[16][6];
        #pragma unroll
        for (int c = 0; c < NC; c++) {
            const int idx = (b*NC + c)*ND + d;
            #pragma unroll
            for (int j = 0; j < 6; j++) pm[c][j] = g_dmap[j*ST + idx];
        }
        float s0 = 0.f, s1 = 0.f;
        #pragma unroll
        for (int c = 0; c < NC; c++) {
            const int idx = (b*NC + c)*ND + d;
            g_dinit0[idx] = s0; g_dinit1[idx] = s1;
            float ns0 = fmaf(pm[c][0], s0, fmaf(pm[c][1], s1, pm[c][4]));
            float ns1 = fmaf(pm[c][2], s0, fmaf(pm[c][3], s1, pm[c][5]));
            s0 = ns0; s1 = ns1;
        }
    } else if (threadIdx.x < NB) {
        const int b = threadIdx.x;
        float ph[16], qh[16], gh[16];
        #pragma unroll
        for (int wc = 0; wc < NC; wc++) {
            const int u = b*NC + wc;
            ph[wc] = g_wmap[0*NB*NC + u];
            qh[wc] = g_wmap[1*NB*NC + u];
            gh[wc] = g_wmap[2*NB*NC + u];
        }
        float P = 1.f, E = 1.f, w = 1.f;
        #pragma unroll
        for (int wc = NC-1; wc >= 0; wc--) {
            const int u = b*NC + wc;
            g_winit[u*3+0] = P; g_winit[u*3+1] = E; g_winit[u*3+2] = w;
            float nw = fmaf(qh[wc], w, gh[wc]*P);
            P *= ph[wc]; E *= qh[wc]; w = nw;
        }
    }
}

// ============================================================
// Fused pass 3: per (b,chunk) block, 256 threads
//  - warp 4 lane 0: backward weight scan for this chunk -> sA/sB
//  - threads 0-127: diag replay, emit y to d_out, k/err into smem
//  - all 256: two weighted 128x128 outer-product partials -> g_part
// dynamic smem: Kf[64][128], Ef[64][128], sA[64], sB[64]
// ============================================================
__global__ __launch_bounds__(256) void fused3_kernel(float* __restrict__ d_out)
{
    extern __shared__ float sm[];
    float* __restrict__ Kf = sm;                 // 8192
    float* __restrict__ Ef = sm + LC*ND;         // 8192
    float* __restrict__ sA = sm + 2*LC*ND;       // 64
    float* __restrict__ sB = sA + LC;            // 64

    const int b = blockIdx.x >> 4, c = blockIdx.x & (NC-1);
    const int t0 = c * LC;
    const int tid = threadIdx.x;

    if (tid == 128) {
        // weight scan for this chunk (descending t)
        const int u = b*NC + c;
        const float4* __restrict__ gp = g_g4 + b*NS + t0;
        float P = g_winit[u*3+0], E = g_winit[u*3+1], w = g_winit[u*3+2];
        #pragma unroll 4
        for (int s = LC-1; s >= 0; s--) {
            float4 g = gp[s];
            float th = g.z;
            sA[s] = -th * w;
            sB[s] = -th * E;
            P *= g.x;
            E *= g.y;
            w  = fmaf(g.y, w, P);   // uses updated P
        }
    }
    if (tid < 128) {
        const int i = tid;
        const float*  __restrict__ kp = g_k + (b*NS + t0)*ND + i;
        const float*  __restrict__ vp = g_v + (b*NS + t0)*ND + i;
        const float*  __restrict__ qp = g_q + (b*NS + t0)*ND + i;
        const float4* __restrict__ gp = g_g4 + b*NS + t0;
        float* __restrict__ op = d_out + (b*NS + t0)*ND + i;

        const int ii = (b*NC + c)*ND + i;
        float dm = g_dinit0[ii], ds = g_dinit1[ii];

        float kA[UG], vA[UG], qA[UG], kB[UG], vB[UG], qB[UG];
        float4 gA[UG], gB[UG];
        #pragma unroll
        for (int s = 0; s < UG; s++) { kA[s]=kp[s*ND]; vA[s]=vp[s*ND]; qA[s]=qp[s*ND]; gA[s]=gp[s]; }

        #pragma unroll
        for (int g = 0; g < NGRP; g++) {
            const bool useA = ((g & 1) == 0);
            if (g + 1 < NGRP) {
                #pragma unroll
                for (int s = 0; s < UG; s++) {
                    int off = ((g+1)*UG + s)*ND;
                    int go  = (g+1)*UG + s;
                    if (useA) { kB[s]=kp[off]; vB[s]=vp[off]; qB[s]=qp[off]; gB[s]=gp[go]; }
                    else      { kA[s]=kp[off]; vA[s]=vp[off]; qA[s]=qp[off]; gA[s]=gp[go]; }
                }
            }
            #pragma unroll
            for (int s = 0; s < UG; s++) {
                float  kk = useA ? kA[s] : kB[s];
                float  vv = useA ? vA[s] : vB[s];
                float  qq = useA ? qA[s] : qB[s];
                float4 gg = useA ? gA[s] : gB[s];
                float om = gg.x, e = gg.y, th = gg.z;
                const int st = g*UG + s;
                op[st*ND] = qq * dm;                  // y_t = q_t * dm_{t-1}
                float err = fmaf(kk, dm, -vv);
                Kf[st*ND + i] = kk;
                Ef[st*ND + i] = err;
                float t1 = th*kk, c2 = t1*vv, d0 = -t1*kk;
                float inner = fmaf(e, ds, c2);
                ds = fmaf(d0, dm, inner);             // S diag update
                dm = fmaf(om, dm, ds);                // M diag update
            }
        }
    }
    __syncthreads();

    // weighted outer-product partials: which=0 -> A (M_final), which=1 -> B (S_final)
    const int tx = tid & 15, ty = tid >> 4;
    #pragma unroll
    for (int which = 0; which < 2; which++) {
        const float* __restrict__ wgt = which ? sB : sA;
        float acc[8][8];
        #pragma unroll
        for (int i = 0; i < 8; i++)
            #pragma unroll
            for (int j = 0; j < 8; j++) acc[i][j] = 0.f;

        for (int s = 0; s < LC; s++) {
            float wv = wgt[s];
            float afr[8], bfr[8];
            *reinterpret_cast<float4*>(&afr[0]) = *reinterpret_cast<const float4*>(&Kf[s*ND + ty*8]);
            *reinterpret_cast<float4*>(&afr[4]) = *reinterpret_cast<const float4*>(&Kf[s*ND + ty*8+4]);
            *reinterpret_cast<float4*>(&bfr[0]) = *reinterpret_cast<const float4*>(&Ef[s*ND + tx*8]);
            *reinterpret_cast<float4*>(&bfr[4]) = *reinterpret_cast<const float4*>(&Ef[s*ND + tx*8+4]);
            #pragma unroll
            for (int i = 0; i < 8; i++) afr[i] *= wv;
            #pragma unroll
            for (int i = 0; i < 8; i++)
                #pragma unroll
                for (int j = 0; j < 8; j++)
                    acc[i][j] = fmaf(afr[i], bfr[j], acc[i][j]);
        }
        float* __restrict__ C = g_part + ((b*2 + which)*NC + c)*ND*ND;
        #pragma unroll
        for (int i = 0; i < 8; i++) {
            #pragma unroll
            for (int j = 0; j < 8; j += 4) {
                *reinterpret_cast<float4*>(&C[(ty*8+i)*ND + tx*8 + j]) =
                    make_float4(acc[i][j], acc[i][j+1], acc[i][j+2], acc[i][j+3]);
            }
        }
    }
}

// ============================================================
// Kernel 5: reduce split partials -> d_out tail
// d_out layout: [outputs(8,1024,128)][M_final(8,128,128)][S_final(8,128,128)]
// ============================================================
__global__ __launch_bounds__(256) void reduce_kernel(float* __restrict__ d_out)
{
    const int gid = blockIdx.x * 256 + threadIdx.x;  // [0, 262144)
    const int which = gid >> 17;
    const int r  = gid & 131071;
    const int b  = r >> 14;
    const int ij = r & 16383;
    const float* __restrict__ p = g_part + ((b*2 + which)*NC)*ND*ND + ij;
    float s = 0.f;
    #pragma unroll
    for (int sp = 0; sp < NC; sp++) s += p[sp*ND*ND];
    d_out[BSD + gid] = s;
}

// ============================================================
extern "C" void kernel_launch(void* const* d_in, const int* in_sizes, int n_in,
                              void* d_out, int out_size)
{
    const float* x  = (const float*)d_in[0];
    const float* Wk = (const float*)d_in[1];
    const float* Wv = (const float*)d_in[2];
    const float* Wq = (const float*)d_in[3];
    const float* Wg = (const float*)d_in[4];
    const float* bg = (const float*)d_in[5];
    float* out = (float*)d_out;

    const int fused_smem = (2*LC*ND + 2*LC) * (int)sizeof(float);  // 66048 B
    cudaFuncSetAttribute(fused3_kernel, cudaFuncAttributeMaxDynamicSharedMemorySize, fused_smem);

    k1_qkv_gates<<<dim3(64, 4), 256>>>(x, Wk, Wv, Wq, Wg, bg);
    pass1_kernel<<<NB*NC + 1, 128>>>();
    pass2_kernel<<<NB + 1, 128>>>();
    fused3_kernel<<<NB*NC, 256, fused_smem>>>(out);
    reduce_kernel<<<1024, 256>>>(out);
}

// round 4
// speedup vs baseline: 4.6192x; 1.0004x over previous
#include <cuda_runtime.h>

#define NB 8
#define NS 1024
#define ND 128
#define NROWS (NB*NS)   // 8192
#define BSD (NB*NS*ND)  // 1048576

#define NC 16           // chunks (shared by diag scan and final gemm splits)
#define LC 64           // steps per chunk
#define UG 8            // prefetch group size
#define NGRP (LC/UG)

// ---- scratch (static device globals; no runtime allocation) ----
__device__ float  g_k[NROWS*ND];
__device__ float  g_v[NROWS*ND];
__device__ float  g_q[NROWS*ND];
__device__ float4 g_g4[NROWS];           // (om=1-a, e, th, 0) per (b,t)
__device__ float  g_dmap[6*NB*NC*ND];    // composed diag maps: m00,m01,m10,m11,v0,v1
__device__ float  g_dinit0[NB*NC*ND];    // dm at chunk entry
__device__ float  g_dinit1[NB*NC*ND];    // ds at chunk entry
__device__ float  g_wmap[3*NB*NC];       // composed weight maps: p^, q^, gamma^
__device__ float  g_winit[NB*NC*3];      // (P,E,w) at chunk entry (backward order)
__device__ float  g_part[NB*2*NC*ND*ND]; // split-K partials

// ============================================================
// Kernel 1: y<3: k/v/q = x@W  (8192x128 @ 128x128), y==3: gates
// ============================================================
__global__ __launch_bounds__(256) void k1_qkv_gates(
    const float* __restrict__ x, const float* __restrict__ Wk,
    const float* __restrict__ Wv, const float* __restrict__ Wq,
    const float* __restrict__ Wg, const float* __restrict__ bg)
{
    const int which = blockIdx.y;
    if (which == 3) {
        const int base = blockIdx.x * 128;
        const int w = threadIdx.x >> 5, lane = threadIdx.x & 31;
        const float b0 = bg[0], b1 = bg[1], b2 = bg[2];
        const float w0a = Wg[lane*3+0],      w0b = Wg[lane*3+1],      w0c = Wg[lane*3+2];
        const float w1a = Wg[(lane+32)*3+0], w1b = Wg[(lane+32)*3+1], w1c = Wg[(lane+32)*3+2];
        const float w2a = Wg[(lane+64)*3+0], w2b = Wg[(lane+64)*3+1], w2c = Wg[(lane+64)*3+2];
        const float w3a = Wg[(lane+96)*3+0], w3b = Wg[(lane+96)*3+1], w3c = Wg[(lane+96)*3+2];
        for (int rr = 0; rr < 16; rr++) {
            const int r = base + w*16 + rr;
            const float* __restrict__ xr = x + r * ND;
            float x0 = xr[lane], x1 = xr[lane+32], x2 = xr[lane+64], x3 = xr[lane+96];
            float s0 = x0*w0a + x1*w1a + x2*w2a + x3*w3a;
            float s1 = x0*w0b + x1*w1b + x2*w2b + x3*w3b;
            float s2 = x0*w0c + x1*w1c + x2*w2c + x3*w3c;
            #pragma unroll
            for (int o = 16; o; o >>= 1) {
                s0 += __shfl_xor_sync(0xffffffffu, s0, o);
                s1 += __shfl_xor_sync(0xffffffffu, s1, o);
                s2 += __shfl_xor_sync(0xffffffffu, s2, o);
            }
            if (lane == 0) {
                float om = 1.f / (1.f + expf(s0 + b0));       // 1 - sigmoid
                float e  = 1.f / (1.f + expf(-(s1 + b1)));
                float th = 1.f / (1.f + expf(-(s2 + b2)));
                g_g4[r] = make_float4(om, e, th, 0.f);
            }
        }
        return;
    }
    const float* __restrict__ W = (which == 0) ? Wk : ((which == 1) ? Wv : Wq);
    float* __restrict__ out = (which == 0) ? g_k : ((which == 1) ? g_v : g_q);
    const int rowBase = blockIdx.x * 128;

    __shared__ float Xs[16][128];
    __shared__ float Ws[16][128];

    const int tid = threadIdx.x;
    const int tx = tid & 15, ty = tid >> 4;

    float acc[8][8];
    #pragma unroll
    for (int i = 0; i < 8; i++)
        #pragma unroll
        for (int j = 0; j < 8; j++) acc[i][j] = 0.f;

    for (int k0 = 0; k0 < 128; k0 += 16) {
        #pragma unroll
        for (int i = 0; i < 2; i++) {
            int e4 = (tid + i*256) * 4;
            int m  = e4 >> 4, kk = e4 & 15;
            float4 xv = *reinterpret_cast<const float4*>(&x[(rowBase + m)*ND + k0 + kk]);
            Xs[kk+0][m] = xv.x; Xs[kk+1][m] = xv.y; Xs[kk+2][m] = xv.z; Xs[kk+3][m] = xv.w;
            int kw = e4 >> 7, n = e4 & 127;
            float4 wv = *reinterpret_cast<const float4*>(&W[(k0 + kw)*ND + n]);
            *reinterpret_cast<float4*>(&Ws[kw][n]) = wv;
        }
        __syncthreads();
        #pragma unroll
        for (int kk = 0; kk < 16; kk++) {
            float afr[8], bfr[8];
            *reinterpret_cast<float4*>(&afr[0]) = *reinterpret_cast<const float4*>(&Xs[kk][ty*8]);
            *reinterpret_cast<float4*>(&afr[4]) = *reinterpret_cast<const float4*>(&Xs[kk][ty*8+4]);
            *reinterpret_cast<float4*>(&bfr[0]) = *reinterpret_cast<const float4*>(&Ws[kk][tx*8]);
            *reinterpret_cast<float4*>(&bfr[4]) = *reinterpret_cast<const float4*>(&Ws[kk][tx*8+4]);
            #pragma unroll
            for (int i = 0; i < 8; i++)
                #pragma unroll
                for (int j = 0; j < 8; j++)
                    acc[i][j] = fmaf(afr[i], bfr[j], acc[i][j]);
        }
        __syncthreads();
    }
    #pragma unroll
    for (int i = 0; i < 8; i++) {
        int m = rowBase + ty*8 + i;
        #pragma unroll
        for (int j = 0; j < 8; j += 4) {
            *reinterpret_cast<float4*>(&out[m*ND + tx*8 + j]) =
                make_float4(acc[i][j], acc[i][j+1], acc[i][j+2], acc[i][j+3]);
        }
    }
}

// ============================================================
// Pass 1: chunk map composition (diag maps + weight maps)
// ============================================================
__global__ __launch_bounds__(128) void pass1_kernel()
{
    const int blk = blockIdx.x;
    if (blk < NB*NC) {
        const int b = blk >> 4, c = blk & (NC-1);
        const int i = threadIdx.x;
        const int t0 = c * LC;
        const float*  __restrict__ kp = g_k + (b*NS + t0)*ND + i;
        const float*  __restrict__ vp = g_v + (b*NS + t0)*ND + i;
        const float4* __restrict__ gp = g_g4 + b*NS + t0;

        float m00=1.f, m01=0.f, m10=0.f, m11=1.f, w0=0.f, w1=0.f;
        float kA[UG], vA[UG], kB[UG], vB[UG];
        float4 gA[UG], gB[UG];
        #pragma unroll
        for (int s = 0; s < UG; s++) { kA[s]=kp[s*ND]; vA[s]=vp[s*ND]; gA[s]=gp[s]; }

        #pragma unroll
        for (int g = 0; g < NGRP; g++) {
            const bool useA = ((g & 1) == 0);
            if (g + 1 < NGRP) {
                #pragma unroll
                for (int s = 0; s < UG; s++) {
                    int off = ((g+1)*UG + s)*ND;
                    int go  = (g+1)*UG + s;
                    if (useA) { kB[s]=kp[off]; vB[s]=vp[off]; gB[s]=gp[go]; }
                    else      { kA[s]=kp[off]; vA[s]=vp[off]; gA[s]=gp[go]; }
                }
            }
            #pragma unroll
            for (int s = 0; s < UG; s++) {
                float  kk = useA ? kA[s] : kB[s];
                float  vv = useA ? vA[s] : vB[s];
                float4 gg = useA ? gA[s] : gB[s];
                float om = gg.x, e = gg.y, th = gg.z;
                float t1 = th*kk, c2 = t1*vv, d0 = -t1*kk, a00 = om + d0;
                float te0 = e*m10, te1 = e*m11;
                float n00 = fmaf(a00, m00, te0), n10 = fmaf(d0, m00, te0);
                float n01 = fmaf(a00, m01, te1), n11 = fmaf(d0, m01, te1);
                float tev = fmaf(e, w1, c2);
                float nw0 = fmaf(a00, w0, tev), nw1 = fmaf(d0, w0, tev);
                m00=n00; m01=n01; m10=n10; m11=n11; w0=nw0; w1=nw1;
            }
        }
        const int base = (b*NC + c)*ND + i;
        const int ST = NB*NC*ND;
        g_dmap[0*ST+base] = m00; g_dmap[1*ST+base] = m01;
        g_dmap[2*ST+base] = m10; g_dmap[3*ST+base] = m11;
        g_dmap[4*ST+base] = w0;  g_dmap[5*ST+base] = w1;
    } else {
        const int u = threadIdx.x;   // (b, wc), 128 units
        const int b = u >> 4, wc = u & (NC-1);
        const float4* __restrict__ gp = g_g4 + b*NS + wc*LC;
        float ph = 1.f, qh = 1.f, gh = 0.f;
        #pragma unroll 4
        for (int s = LC-1; s >= 0; s--) {
            float4 g = gp[s];
            float p = g.x, q = g.y;
            gh = fmaf(q, gh, p*ph);   // uses old ph
            ph *= p;
            qh *= q;
        }
        g_wmap[0*NB*NC + u] = ph;
        g_wmap[1*NB*NC + u] = qh;
        g_wmap[2*NB*NC + u] = gh;
    }
}

// ============================================================
// Pass 2: sequential combine over chunk maps -> chunk-entry states
// ============================================================
__global__ __launch_bounds__(128) void pass2_kernel()
{
    if (blockIdx.x < NB) {
        const int b = blockIdx.x, d = threadIdx.x;
        const int ST = NB*NC*ND;
        float pm[16][6];
        #pragma unroll
        for (int c = 0; c < NC; c++) {
            const int idx = (b*NC + c)*ND + d;
            #pragma unroll
            for (int j = 0; j < 6; j++) pm[c][j] = g_dmap[j*ST + idx];
        }
        float s0 = 0.f, s1 = 0.f;
        #pragma unroll
        for (int c = 0; c < NC; c++) {
            const int idx = (b*NC + c)*ND + d;
            g_dinit0[idx] = s0; g_dinit1[idx] = s1;
            float ns0 = fmaf(pm[c][0], s0, fmaf(pm[c][1], s1, pm[c][4]));
            float ns1 = fmaf(pm[c][2], s0, fmaf(pm[c][3], s1, pm[c][5]));
            s0 = ns0; s1 = ns1;
        }
    } else if (threadIdx.x < NB) {
        const int b = threadIdx.x;
        float ph[16], qh[16], gh[16];
        #pragma unroll
        for (int wc = 0; wc < NC; wc++) {
            const int u = b*NC + wc;
            ph[wc] = g_wmap[0*NB*NC + u];
            qh[wc] = g_wmap[1*NB*NC + u];
            gh[wc] = g_wmap[2*NB*NC + u];
        }
        float P = 1.f, E = 1.f, w = 1.f;
        #pragma unroll
        for (int wc = NC-1; wc >= 0; wc--) {
            const int u = b*NC + wc;
            g_winit[u*3+0] = P; g_winit[u*3+1] = E; g_winit[u*3+2] = w;
            float nw = fmaf(qh[wc], w, gh[wc]*P);
            P *= ph[wc]; E *= qh[wc]; w = nw;
        }
    }
}

// ============================================================
// Fused pass 3: per (b,chunk) block, 512 threads
//  - tid 128: backward weight scan for this chunk -> sA/sB
//  - tid 0-127: diag replay, emit y to d_out, k/err into smem
//  - then warps 0-7 compute A-weighted partial, warps 8-15 B-weighted
// dynamic smem: Kf[64][128], Ef[64][128], sA[64], sB[64]
// ============================================================
__global__ __launch_bounds__(512) void fused3_kernel(float* __restrict__ d_out)
{
    extern __shared__ float sm[];
    float* __restrict__ Kf = sm;                 // 8192
    float* __restrict__ Ef = sm + LC*ND;         // 8192
    float* __restrict__ sA = sm + 2*LC*ND;       // 64
    float* __restrict__ sB = sA + LC;            // 64

    const int b = blockIdx.x >> 4, c = blockIdx.x & (NC-1);
    const int t0 = c * LC;
    const int tid = threadIdx.x;

    if (tid == 128) {
        // weight scan for this chunk (descending t)
        const int u = b*NC + c;
        const float4* __restrict__ gp = g_g4 + b*NS + t0;
        float P = g_winit[u*3+0], E = g_winit[u*3+1], w = g_winit[u*3+2];
        #pragma unroll 4
        for (int s = LC-1; s >= 0; s--) {
            float4 g = gp[s];
            float th = g.z;
            sA[s] = -th * w;
            sB[s] = -th * E;
            P *= g.x;
            E *= g.y;
            w  = fmaf(g.y, w, P);   // uses updated P
        }
    }
    if (tid < 128) {
        const int i = tid;
        const float*  __restrict__ kp = g_k + (b*NS + t0)*ND + i;
        const float*  __restrict__ vp = g_v + (b*NS + t0)*ND + i;
        const float*  __restrict__ qp = g_q + (b*NS + t0)*ND + i;
        const float4* __restrict__ gp = g_g4 + b*NS + t0;
        float* __restrict__ op = d_out + (b*NS + t0)*ND + i;

        const int ii = (b*NC + c)*ND + i;
        float dm = g_dinit0[ii], ds = g_dinit1[ii];

        float kA[UG], vA[UG], qA[UG], kB[UG], vB[UG], qB[UG];
        float4 gA[UG], gB[UG];
        #pragma unroll
        for (int s = 0; s < UG; s++) { kA[s]=kp[s*ND]; vA[s]=vp[s*ND]; qA[s]=qp[s*ND]; gA[s]=gp[s]; }

        #pragma unroll
        for (int g = 0; g < NGRP; g++) {
            const bool useA = ((g & 1) == 0);
            if (g + 1 < NGRP) {
                #pragma unroll
                for (int s = 0; s < UG; s++) {
                    int off = ((g+1)*UG + s)*ND;
                    int go  = (g+1)*UG + s;
                    if (useA) { kB[s]=kp[off]; vB[s]=vp[off]; qB[s]=qp[off]; gB[s]=gp[go]; }
                    else      { kA[s]=kp[off]; vA[s]=vp[off]; qA[s]=qp[off]; gA[s]=gp[go]; }
                }
            }
            #pragma unroll
            for (int s = 0; s < UG; s++) {
                float  kk = useA ? kA[s] : kB[s];
                float  vv = useA ? vA[s] : vB[s];
                float  qq = useA ? qA[s] : qB[s];
                float4 gg = useA ? gA[s] : gB[s];
                float om = gg.x, e = gg.y, th = gg.z;
                const int st = g*UG + s;
                op[st*ND] = qq * dm;                  // y_t = q_t * dm_{t-1}
                float err = fmaf(kk, dm, -vv);
                Kf[st*ND + i] = kk;
                Ef[st*ND + i] = err;
                float t1 = th*kk, c2 = t1*vv, d0 = -t1*kk;
                float inner = fmaf(e, ds, c2);
                ds = fmaf(d0, dm, inner);             // S diag update
                dm = fmaf(om, dm, ds);                // M diag update
            }
        }
    }
    __syncthreads();

    // weighted outer-product partials: half 0 -> A (M_final), half 1 -> B (S_final)
    const int which = tid >> 8;          // 0 or 1
    const int t256 = tid & 255;
    const int tx = t256 & 15, ty = t256 >> 4;
    const float* __restrict__ wgt = which ? sB : sA;

    float acc[8][8];
    #pragma unroll
    for (int i = 0; i < 8; i++)
        #pragma unroll
        for (int j = 0; j < 8; j++) acc[i][j] = 0.f;

    #pragma unroll 4
    for (int s = 0; s < LC; s++) {
        float wv = wgt[s];
        float afr[8], bfr[8];
        *reinterpret_cast<float4*>(&afr[0]) = *reinterpret_cast<const float4*>(&Kf[s*ND + ty*8]);
        *reinterpret_cast<float4*>(&afr[4]) = *reinterpret_cast<const float4*>(&Kf[s*ND + ty*8+4]);
        *reinterpret_cast<float4*>(&bfr[0]) = *reinterpret_cast<const float4*>(&Ef[s*ND + tx*8]);
        *reinterpret_cast<float4*>(&bfr[4]) = *reinterpret_cast<const float4*>(&Ef[s*ND + tx*8+4]);
        #pragma unroll
        for (int i = 0; i < 8; i++) afr[i] *= wv;
        #pragma unroll
        for (int i = 0; i < 8; i++)
            #pragma unroll
            for (int j = 0; j < 8; j++)
                acc[i][j] = fmaf(afr[i], bfr[j], acc[i][j]);
    }
    float* __restrict__ C = g_part + ((b*2 + which)*NC + c)*ND*ND;
    #pragma unroll
    for (int i = 0; i < 8; i++) {
        #pragma unroll
        for (int j = 0; j < 8; j += 4) {
            *reinterpret_cast<float4*>(&C[(ty*8+i)*ND + tx*8 + j]) =
                make_float4(acc[i][j], acc[i][j+1], acc[i][j+2], acc[i][j+3]);
        }
    }
}

// ============================================================
// Kernel 5: reduce split partials -> d_out tail (float4)
// d_out layout: [outputs(8,1024,128)][M_final(8,128,128)][S_final(8,128,128)]
// ============================================================
__global__ __launch_bounds__(256) void reduce_kernel(float* __restrict__ d_out)
{
    const int g4 = blockIdx.x * 256 + threadIdx.x;   // [0, 65536) float4 units
    const int gid = g4 * 4;
    const int which = gid >> 17;
    const int r  = gid & 131071;
    const int b  = r >> 14;
    const int ij = r & 16383;
    const float* __restrict__ p = g_part + ((b*2 + which)*NC)*ND*ND + ij;
    float4 s = make_float4(0.f, 0.f, 0.f, 0.f);
    #pragma unroll
    for (int sp = 0; sp < NC; sp++) {
        float4 v = *reinterpret_cast<const float4*>(&p[sp*ND*ND]);
        s.x += v.x; s.y += v.y; s.z += v.z; s.w += v.w;
    }
    *reinterpret_cast<float4*>(&d_out[BSD + gid]) = s;
}

// ============================================================
extern "C" void kernel_launch(void* const* d_in, const int* in_sizes, int n_in,
                              void* d_out, int out_size)
{
    const float* x  = (const float*)d_in[0];
    const float* Wk = (const float*)d_in[1];
    const float* Wv = (const float*)d_in[2];
    const float* Wq = (const float*)d_in[3];
    const float* Wg = (const float*)d_in[4];
    const float* bg = (const float*)d_in[5];
    float* out = (float*)d_out;

    const int fused_smem = (2*LC*ND + 2*LC) * (int)sizeof(float);  // 66048 B
    cudaFuncSetAttribute(fused3_kernel, cudaFuncAttributeMaxDynamicSharedMemorySize, fused_smem);

    k1_qkv_gates<<<dim3(64, 4), 256>>>(x, Wk, Wv, Wq, Wg, bg);
    pass1_kernel<<<NB*NC + 1, 128>>>();
    pass2_kernel<<<NB + 1, 128>>>();
    fused3_kernel<<<NB*NC, 512, fused_smem>>>(out);
    reduce_kernel<<<256, 256>>>(out);
}

// round 5
// speedup vs baseline: 5.2254x; 1.1312x over previous
#include <cuda_runtime.h>
#include <cuda_bf16.h>

#define NB 8
#define NS 1024
#define ND 128
#define NROWS (NB*NS)   // 8192
#define BSD (NB*NS*ND)  // 1048576

#define NC 16           // chunks (shared by diag scan and final gemm splits)
#define LC 64           // steps per chunk
#define UG 8            // prefetch group size
#define NGRP (LC/UG)

#define KP 72           // padded bf16 k-stride in smem (64 + 8) -> conflict-free frags

// ---- scratch (static device globals; no runtime allocation) ----
__device__ float  g_k[NROWS*ND];
__device__ float  g_v[NROWS*ND];
__device__ float  g_q[NROWS*ND];
__device__ float4 g_g4[NROWS];           // (om=1-a, e, th, 0) per (b,t)
__device__ float  g_dmap[6*NB*NC*ND];    // composed diag maps
__device__ float  g_dinit0[NB*NC*ND];
__device__ float  g_dinit1[NB*NC*ND];
__device__ float  g_wmap[3*NB*NC];
__device__ float  g_winit[NB*NC*3];
__device__ float  g_part[NB*2*NC*ND*ND];

// ---- mma.sync m16n8k16 bf16 -> f32 ----
__device__ __forceinline__ void mma16816(float* c, const unsigned* a, const unsigned* b)
{
    asm volatile(
        "mma.sync.aligned.m16n8k16.row.col.f32.bf16.bf16.f32 "
        "{%0,%1,%2,%3}, {%4,%5,%6,%7}, {%8,%9}, {%0,%1,%2,%3};"
        : "+f"(c[0]), "+f"(c[1]), "+f"(c[2]), "+f"(c[3])
        : "r"(a[0]), "r"(a[1]), "r"(a[2]), "r"(a[3]), "r"(b[0]), "r"(b[1]));
}

// ============================================================
// Kernel 1: y<3: k/v/q = x@W via bf16-split tensor mma; y==3: gates
// block = 256 threads; output tile 128x128, K processed in 2 chunks of 64
// dyn smem: XH[128][KP], XL[128][KP], WTH[128][KP], WTL[128][KP] (bf16)
// ============================================================
__global__ __launch_bounds__(256) void k1_qkv_gates(
    const float* __restrict__ x, const float* __restrict__ Wk,
    const float* __restrict__ Wv, const float* __restrict__ Wq,
    const float* __restrict__ Wg, const float* __restrict__ bg)
{
    const int which = blockIdx.y;
    if (which == 3) {
        const int base = blockIdx.x * 128;
        const int w = threadIdx.x >> 5, lane = threadIdx.x & 31;
        const float b0 = bg[0], b1 = bg[1], b2 = bg[2];
        const float w0a = Wg[lane*3+0],      w0b = Wg[lane*3+1],      w0c = Wg[lane*3+2];
        const float w1a = Wg[(lane+32)*3+0], w1b = Wg[(lane+32)*3+1], w1c = Wg[(lane+32)*3+2];
        const float w2a = Wg[(lane+64)*3+0], w2b = Wg[(lane+64)*3+1], w2c = Wg[(lane+64)*3+2];
        const float w3a = Wg[(lane+96)*3+0], w3b = Wg[(lane+96)*3+1], w3c = Wg[(lane+96)*3+2];
        for (int rr = 0; rr < 16; rr++) {
            const int r = base + w*16 + rr;
            const float* __restrict__ xr = x + r * ND;
            float x0 = xr[lane], x1 = xr[lane+32], x2 = xr[lane+64], x3 = xr[lane+96];
            float s0 = x0*w0a + x1*w1a + x2*w2a + x3*w3a;
            float s1 = x0*w0b + x1*w1b + x2*w2b + x3*w3b;
            float s2 = x0*w0c + x1*w1c + x2*w2c + x3*w3c;
            #pragma unroll
            for (int o = 16; o; o >>= 1) {
                s0 += __shfl_xor_sync(0xffffffffu, s0, o);
                s1 += __shfl_xor_sync(0xffffffffu, s1, o);
                s2 += __shfl_xor_sync(0xffffffffu, s2, o);
            }
            if (lane == 0) {
                float om = 1.f / (1.f + expf(s0 + b0));       // 1 - sigmoid
                float e  = 1.f / (1.f + expf(-(s1 + b1)));
                float th = 1.f / (1.f + expf(-(s2 + b2)));
                g_g4[r] = make_float4(om, e, th, 0.f);
            }
        }
        return;
    }
    extern __shared__ __nv_bfloat16 bsm[];
    __nv_bfloat16* __restrict__ XH  = bsm;              // 128*KP
    __nv_bfloat16* __restrict__ XL  = XH  + 128*KP;
    __nv_bfloat16* __restrict__ WTH = XL  + 128*KP;     // transposed W: [n][k]
    __nv_bfloat16* __restrict__ WTL = WTH + 128*KP;

    const float* __restrict__ W = (which == 0) ? Wk : ((which == 1) ? Wv : Wq);
    float* __restrict__ out = (which == 0) ? g_k : ((which == 1) ? g_v : g_q);
    const int rowBase = blockIdx.x * 128;

    const int tid  = threadIdx.x;
    const int lane = tid & 31;
    const int warp = tid >> 5;
    const int g    = lane >> 2;          // groupID
    const int tig  = lane & 3;           // thread-in-group
    const int wm   = warp >> 1;          // 0..3  (m block of 32)
    const int wn   = warp & 1;           // 0..1  (n block of 64)

    float acc[2][8][4];
    #pragma unroll
    for (int mt = 0; mt < 2; mt++)
        #pragma unroll
        for (int nt = 0; nt < 8; nt++)
            #pragma unroll
            for (int r = 0; r < 4; r++) acc[mt][nt][r] = 0.f;

    for (int k0 = 0; k0 < 128; k0 += 64) {
        // ---- stage X chunk: rows 0..127, cols k0..k0+63, split hi/lo ----
        {
            const int row = tid >> 1, half = tid & 1;
            const float* __restrict__ src = x + (rowBase + row)*ND + k0 + half*32;
            __nv_bfloat16* __restrict__ dh = XH + row*KP + half*32;
            __nv_bfloat16* __restrict__ dl = XL + row*KP + half*32;
            #pragma unroll
            for (int j = 0; j < 8; j++) {
                float4 v = *reinterpret_cast<const float4*>(&src[j*4]);
                #pragma unroll
                for (int i = 0; i < 4; i++) {
                    float f = (&v.x)[i];
                    __nv_bfloat16 h = __float2bfloat16_rn(f);
                    float r = f - __bfloat162float(h);
                    dh[j*4+i] = h;
                    dl[j*4+i] = __float2bfloat16_rn(r);
                }
            }
        }
        // ---- stage W chunk transposed: WT[n][kk], kk in [0,64) ----
        {
            const int krow = tid >> 2, nb = (tid & 3)*32;
            const float* __restrict__ src = W + (k0 + krow)*ND + nb;
            #pragma unroll
            for (int j = 0; j < 8; j++) {
                float4 v = *reinterpret_cast<const float4*>(&src[j*4]);
                #pragma unroll
                for (int i = 0; i < 4; i++) {
                    float f = (&v.x)[i];
                    __nv_bfloat16 h = __float2bfloat16_rn(f);
                    float r = f - __bfloat162float(h);
                    const int n = nb + j*4 + i;
                    WTH[n*KP + krow] = h;
                    WTL[n*KP + krow] = __float2bfloat16_rn(r);
                }
            }
        }
        __syncthreads();

        #pragma unroll
        for (int kk = 0; kk < 64; kk += 16) {
            unsigned ah[2][4], al[2][4];
            #pragma unroll
            for (int mt = 0; mt < 2; mt++) {
                const int r0 = (wm*32 + mt*16 + g)*KP + kk + tig*2;
                const int r1 = r0 + 8*KP;
                ah[mt][0] = *reinterpret_cast<const unsigned*>(&XH[r0]);
                ah[mt][1] = *reinterpret_cast<const unsigned*>(&XH[r1]);
                ah[mt][2] = *reinterpret_cast<const unsigned*>(&XH[r0 + 8]);
                ah[mt][3] = *reinterpret_cast<const unsigned*>(&XH[r1 + 8]);
                al[mt][0] = *reinterpret_cast<const unsigned*>(&XL[r0]);
                al[mt][1] = *reinterpret_cast<const unsigned*>(&XL[r1]);
                al[mt][2] = *reinterpret_cast<const unsigned*>(&XL[r0 + 8]);
                al[mt][3] = *reinterpret_cast<const unsigned*>(&XL[r1 + 8]);
            }
            #pragma unroll
            for (int nt = 0; nt < 8; nt++) {
                const int bo = (wn*64 + nt*8 + g)*KP + kk + tig*2;
                unsigned bh[2], bl[2];
                bh[0] = *reinterpret_cast<const unsigned*>(&WTH[bo]);
                bh[1] = *reinterpret_cast<const unsigned*>(&WTH[bo + 8]);
                bl[0] = *reinterpret_cast<const unsigned*>(&WTL[bo]);
                bl[1] = *reinterpret_cast<const unsigned*>(&WTL[bo + 8]);
                #pragma unroll
                for (int mt = 0; mt < 2; mt++) {
                    mma16816(acc[mt][nt], ah[mt], bh);   // hh
                    mma16816(acc[mt][nt], ah[mt], bl);   // hl
                    mma16816(acc[mt][nt], al[mt], bh);   // lh
                }
            }
        }
        __syncthreads();
    }

    // ---- epilogue: C frag (g, tig*2) layout ----
    #pragma unroll
    for (int mt = 0; mt < 2; mt++) {
        const int r0 = rowBase + wm*32 + mt*16 + g;
        const int r1 = r0 + 8;
        #pragma unroll
        for (int nt = 0; nt < 8; nt++) {
            const int c0 = wn*64 + nt*8 + tig*2;
            *reinterpret_cast<float2*>(&out[r0*ND + c0]) = make_float2(acc[mt][nt][0], acc[mt][nt][1]);
            *reinterpret_cast<float2*>(&out[r1*ND + c0]) = make_float2(acc[mt][nt][2], acc[mt][nt][3]);
        }
    }
}

// ============================================================
// Pass 1: chunk map composition (diag maps + weight maps)
// ============================================================
__global__ __launch_bounds__(128) void pass1_kernel()
{
    const int blk = blockIdx.x;
    if (blk < NB*NC) {
        const int b = blk >> 4, c = blk & (NC-1);
        const int i = threadIdx.x;
        const int t0 = c * LC;
        const float*  __restrict__ kp = g_k + (b*NS + t0)*ND + i;
        const float*  __restrict__ vp = g_v + (b*NS + t0)*ND + i;
        const float4* __restrict__ gp = g_g4 + b*NS + t0;

        float m00=1.f, m01=0.f, m10=0.f, m11=1.f, w0=0.f, w1=0.f;
        float kA[UG], vA[UG], kB[UG], vB[UG];
        float4 gA[UG], gB[UG];
        #pragma unroll
        for (int s = 0; s < UG; s++) { kA[s]=kp[s*ND]; vA[s]=vp[s*ND]; gA[s]=gp[s]; }

        #pragma unroll
        for (int g = 0; g < NGRP; g++) {
            const bool useA = ((g & 1) == 0);
            if (g + 1 < NGRP) {
                #pragma unroll
                for (int s = 0; s < UG; s++) {
                    int off = ((g+1)*UG + s)*ND;
                    int go  = (g+1)*UG + s;
                    if (useA) { kB[s]=kp[off]; vB[s]=vp[off]; gB[s]=gp[go]; }
                    else      { kA[s]=kp[off]; vA[s]=vp[off]; gA[s]=gp[go]; }
                }
            }
            #pragma unroll
            for (int s = 0; s < UG; s++) {
                float  kk = useA ? kA[s] : kB[s];
                float  vv = useA ? vA[s] : vB[s];
                float4 gg = useA ? gA[s] : gB[s];
                float om = gg.x, e = gg.y, th = gg.z;
                float t1 = th*kk, c2 = t1*vv, d0 = -t1*kk, a00 = om + d0;
                float te0 = e*m10, te1 = e*m11;
                float n00 = fmaf(a00, m00, te0), n10 = fmaf(d0, m00, te0);
                float n01 = fmaf(a00, m01, te1), n11 = fmaf(d0, m01, te1);
                float tev = fmaf(e, w1, c2);
                float nw0 = fmaf(a00, w0, tev), nw1 = fmaf(d0, w0, tev);
                m00=n00; m01=n01; m10=n10; m11=n11; w0=nw0; w1=nw1;
            }
        }
        const int base = (b*NC + c)*ND + i;
        const int ST = NB*NC*ND;
        g_dmap[0*ST+base] = m00; g_dmap[1*ST+base] = m01;
        g_dmap[2*ST+base] = m10; g_dmap[3*ST+base] = m11;
        g_dmap[4*ST+base] = w0;  g_dmap[5*ST+base] = w1;
    } else {
        const int u = threadIdx.x;   // (b, wc), 128 units
        const int b = u >> 4, wc = u & (NC-1);
        const float4* __restrict__ gp = g_g4 + b*NS + wc*LC;
        float ph = 1.f, qh = 1.f, gh = 0.f;
        #pragma unroll 4
        for (int s = LC-1; s >= 0; s--) {
            float4 g = gp[s];
            float p = g.x, q = g.y;
            gh = fmaf(q, gh, p*ph);   // uses old ph
            ph *= p;
            qh *= q;
        }
        g_wmap[0*NB*NC + u] = ph;
        g_wmap[1*NB*NC + u] = qh;
        g_wmap[2*NB*NC + u] = gh;
    }
}

// ============================================================
// Pass 2: sequential combine over chunk maps -> chunk-entry states
// ============================================================
__global__ __launch_bounds__(128) void pass2_kernel()
{
    if (blockIdx.x < NB) {
        const int b = blockIdx.x, d = threadIdx.x;
        const int ST = NB*NC*ND;
        float pm[16][6];
        #pragma unroll
        for (int c = 0; c < NC; c++) {
            const int idx = (b*NC + c)*ND + d;
            #pragma unroll
            for (int j = 0; j < 6; j++) pm[c][j] = g_dmap[j*ST + idx];
        }
        float s0 = 0.f, s1 = 0.f;
        #pragma unroll
        for (int c = 0; c < NC; c++) {
            const int idx = (b*NC + c)*ND + d;
            g_dinit0[idx] = s0; g_dinit1[idx] = s1;
            float ns0 = fmaf(pm[c][0], s0, fmaf(pm[c][1], s1, pm[c][4]));
            float ns1 = fmaf(pm[c][2], s0, fmaf(pm[c][3], s1, pm[c][5]));
            s0 = ns0; s1 = ns1;
        }
    } else if (threadIdx.x < NB) {
        const int b = threadIdx.x;
        float ph[16], qh[16], gh[16];
        #pragma unroll
        for (int wc = 0; wc < NC; wc++) {
            const int u = b*NC + wc;
            ph[wc] = g_wmap[0*NB*NC + u];
            qh[wc] = g_wmap[1*NB*NC + u];
            gh[wc] = g_wmap[2*NB*NC + u];
        }
        float P = 1.f, E = 1.f, w = 1.f;
        #pragma unroll
        for (int wc = NC-1; wc >= 0; wc--) {
            const int u = b*NC + wc;
            g_winit[u*3+0] = P; g_winit[u*3+1] = E; g_winit[u*3+2] = w;
            float nw = fmaf(qh[wc], w, gh[wc]*P);
            P *= ph[wc]; E *= qh[wc]; w = nw;
        }
    }
}

// ============================================================
// Fused pass 3: per (b,chunk) block, 512 threads
// ============================================================
__global__ __launch_bounds__(512) void fused3_kernel(float* __restrict__ d_out)
{
    extern __shared__ float sm[];
    float* __restrict__ Kf = sm;                 // 8192
    float* __restrict__ Ef = sm + LC*ND;         // 8192
    float* __restrict__ sA = sm + 2*LC*ND;       // 64
    float* __restrict__ sB = sA + LC;            // 64

    const int b = blockIdx.x >> 4, c = blockIdx.x & (NC-1);
    const int t0 = c * LC;
    const int tid = threadIdx.x;

    if (tid == 128) {
        const int u = b*NC + c;
        const float4* __restrict__ gp = g_g4 + b*NS + t0;
        float P = g_winit[u*3+0], E = g_winit[u*3+1], w = g_winit[u*3+2];
        #pragma unroll 4
        for (int s = LC-1; s >= 0; s--) {
            float4 g = gp[s];
            float th = g.z;
            sA[s] = -th * w;
            sB[s] = -th * E;
            P *= g.x;
            E *= g.y;
            w  = fmaf(g.y, w, P);
        }
    }
    if (tid < 128) {
        const int i = tid;
        const float*  __restrict__ kp = g_k + (b*NS + t0)*ND + i;
        const float*  __restrict__ vp = g_v + (b*NS + t0)*ND + i;
        const float*  __restrict__ qp = g_q + (b*NS + t0)*ND + i;
        const float4* __restrict__ gp = g_g4 + b*NS + t0;
        float* __restrict__ op = d_out + (b*NS + t0)*ND + i;

        const int ii = (b*NC + c)*ND + i;
        float dm = g_dinit0[ii], ds = g_dinit1[ii];

        float kA[UG], vA[UG], qA[UG], kB[UG], vB[UG], qB[UG];
        float4 gA[UG], gB[UG];
        #pragma unroll
        for (int s = 0; s < UG; s++) { kA[s]=kp[s*ND]; vA[s]=vp[s*ND]; qA[s]=qp[s*ND]; gA[s]=gp[s]; }

        #pragma unroll
        for (int g = 0; g < NGRP; g++) {
            const bool useA = ((g & 1) == 0);
            if (g + 1 < NGRP) {
                #pragma unroll
                for (int s = 0; s < UG; s++) {
                    int off = ((g+1)*UG + s)*ND;
                    int go  = (g+1)*UG + s;
                    if (useA) { kB[s]=kp[off]; vB[s]=vp[off]; qB[s]=qp[off]; gB[s]=gp[go]; }
                    else      { kA[s]=kp[off]; vA[s]=vp[off]; qA[s]=qp[off]; gA[s]=gp[go]; }
                }
            }
            #pragma unroll
            for (int s = 0; s < UG; s++) {
                float  kk = useA ? kA[s] : kB[s];
                float  vv = useA ? vA[s] : vB[s];
                float  qq = useA ? qA[s] : qB[s];
                float4 gg = useA ? gA[s] : gB[s];
                float om = gg.x, e = gg.y, th = gg.z;
                const int st = g*UG + s;
                op[st*ND] = qq * dm;
                float err = fmaf(kk, dm, -vv);
                Kf[st*ND + i] = kk;
                Ef[st*ND + i] = err;
                float t1 = th*kk, c2 = t1*vv, d0 = -t1*kk;
                float inner = fmaf(e, ds, c2);
                ds = fmaf(d0, dm, inner);
                dm = fmaf(om, dm, ds);
            }
        }
    }
    __syncthreads();

    const int which = tid >> 8;
    const int t256 = tid & 255;
    const int tx = t256 & 15, ty = t256 >> 4;
    const float* __restrict__ wgt = which ? sB : sA;

    float acc[8][8];
    #pragma unroll
    for (int i = 0; i < 8; i++)
        #pragma unroll
        for (int j = 0; j < 8; j++) acc[i][j] = 0.f;

    #pragma unroll 4
    for (int s = 0; s < LC; s++) {
        float wv = wgt[s];
        float afr[8], bfr[8];
        *reinterpret_cast<float4*>(&afr[0]) = *reinterpret_cast<const float4*>(&Kf[s*ND + ty*8]);
        *reinterpret_cast<float4*>(&afr[4]) = *reinterpret_cast<const float4*>(&Kf[s*ND + ty*8+4]);
        *reinterpret_cast<float4*>(&bfr[0]) = *reinterpret_cast<const float4*>(&Ef[s*ND + tx*8]);
        *reinterpret_cast<float4*>(&bfr[4]) = *reinterpret_cast<const float4*>(&Ef[s*ND + tx*8+4]);
        #pragma unroll
        for (int i = 0; i < 8; i++) afr[i] *= wv;
        #pragma unroll
        for (int i = 0; i < 8; i++)
            #pragma unroll
            for (int j = 0; j < 8; j++)
                acc[i][j] = fmaf(afr[i], bfr[j], acc[i][j]);
    }
    float* __restrict__ C = g_part + ((b*2 + which)*NC + c)*ND*ND;
    #pragma unroll
    for (int i = 0; i < 8; i++) {
        #pragma unroll
        for (int j = 0; j < 8; j += 4) {
            *reinterpret_cast<float4*>(&C[(ty*8+i)*ND + tx*8 + j]) =
                make_float4(acc[i][j], acc[i][j+1], acc[i][j+2], acc[i][j+3]);
        }
    }
}

// ============================================================
// Kernel 5: reduce split partials -> d_out tail (float4)
// ============================================================
__global__ __launch_bounds__(256) void reduce_kernel(float* __restrict__ d_out)
{
    const int g4 = blockIdx.x * 256 + threadIdx.x;   // [0, 65536) float4 units
    const int gid = g4 * 4;
    const int which = gid >> 17;
    const int r  = gid & 131071;
    const int b  = r >> 14;
    const int ij = r & 16383;
    const float* __restrict__ p = g_part + ((b*2 + which)*NC)*ND*ND + ij;
    float4 s = make_float4(0.f, 0.f, 0.f, 0.f);
    #pragma unroll
    for (int sp = 0; sp < NC; sp++) {
        float4 v = *reinterpret_cast<const float4*>(&p[sp*ND*ND]);
        s.x += v.x; s.y += v.y; s.z += v.z; s.w += v.w;
    }
    *reinterpret_cast<float4*>(&d_out[BSD + gid]) = s;
}

// ============================================================
extern "C" void kernel_launch(void* const* d_in, const int* in_sizes, int n_in,
                              void* d_out, int out_size)
{
    const float* x  = (const float*)d_in[0];
    const float* Wk = (const float*)d_in[1];
    const float* Wv = (const float*)d_in[2];
    const float* Wq = (const float*)d_in[3];
    const float* Wg = (const float*)d_in[4];
    const float* bg = (const float*)d_in[5];
    float* out = (float*)d_out;

    const int k1_smem = 4 * 128 * KP * (int)sizeof(__nv_bfloat16);  // 73728 B
    const int fused_smem = (2*LC*ND + 2*LC) * (int)sizeof(float);   // 66048 B
    cudaFuncSetAttribute(k1_qkv_gates, cudaFuncAttributeMaxDynamicSharedMemorySize, k1_smem);
    cudaFuncSetAttribute(fused3_kernel, cudaFuncAttributeMaxDynamicSharedMemorySize, fused_smem);

    k1_qkv_gates<<<dim3(64, 4), 256, k1_smem>>>(x, Wk, Wv, Wq, Wg, bg);
    pass1_kernel<<<NB*NC + 1, 128>>>();
    pass2_kernel<<<NB + 1, 128>>>();
    fused3_kernel<<<NB*NC, 512, fused_smem>>>(out);
    reduce_kernel<<<256, 256>>>(out);
}

// round 6
// speedup vs baseline: 5.6617x; 1.0835x over previous
#include <cuda_runtime.h>
#include <cuda_bf16.h>

#define NB 8
#define NS 1024
#define ND 128
#define NROWS (NB*NS)   // 8192
#define BSD (NB*NS*ND)  // 1048576

#define NC 16           // chunks (shared by diag scan and final gemm splits)
#define LC 64           // steps per chunk
#define UG 8            // prefetch group size
#define NGRP (LC/UG)

#define KP 72           // padded bf16 k-stride in smem (conflict-free frag loads)

// ---- scratch (static device globals; no runtime allocation) ----
__device__ float  g_k[NROWS*ND];
__device__ float  g_v[NROWS*ND];
__device__ float  g_q[NROWS*ND];
__device__ float4 g_g4[NROWS];           // (om=1-a, e, th, 0) per (b,t)
__device__ float  g_dmap[6*NB*NC*ND];    // composed diag maps
__device__ float  g_dinit0[NB*NC*ND];
__device__ float  g_dinit1[NB*NC*ND];
__device__ float  g_wmap[3*NB*NC];
__device__ float  g_winit[NB*NC*3];
__device__ float  g_part[NB*2*NC*ND*ND];

// ---- mma.sync m16n8k16 bf16 -> f32 ----
__device__ __forceinline__ void mma16816(float* c, const unsigned* a, const unsigned* b)
{
    asm volatile(
        "mma.sync.aligned.m16n8k16.row.col.f32.bf16.bf16.f32 "
        "{%0,%1,%2,%3}, {%4,%5,%6,%7}, {%8,%9}, {%0,%1,%2,%3};"
        : "+f"(c[0]), "+f"(c[1]), "+f"(c[2]), "+f"(c[3])
        : "r"(a[0]), "r"(a[1]), "r"(a[2]), "r"(a[3]), "r"(b[0]), "r"(b[1]));
}

__device__ __forceinline__ void bf16split(float f, __nv_bfloat16& h, __nv_bfloat16& l)
{
    h = __float2bfloat16_rn(f);
    l = __float2bfloat16_rn(f - __bfloat162float(h));
}

// ============================================================
// Kernel 1: y<3: k/v/q = x@W via bf16-split tensor mma; y==3: gates
// ============================================================
__global__ __launch_bounds__(256) void k1_qkv_gates(
    const float* __restrict__ x, const float* __restrict__ Wk,
    const float* __restrict__ Wv, const float* __restrict__ Wq,
    const float* __restrict__ Wg, const float* __restrict__ bg)
{
    const int which = blockIdx.y;
    if (which == 3) {
        const int base = blockIdx.x * 128;
        const int w = threadIdx.x >> 5, lane = threadIdx.x & 31;
        const float b0 = bg[0], b1 = bg[1], b2 = bg[2];
        const float w0a = Wg[lane*3+0],      w0b = Wg[lane*3+1],      w0c = Wg[lane*3+2];
        const float w1a = Wg[(lane+32)*3+0], w1b = Wg[(lane+32)*3+1], w1c = Wg[(lane+32)*3+2];
        const float w2a = Wg[(lane+64)*3+0], w2b = Wg[(lane+64)*3+1], w2c = Wg[(lane+64)*3+2];
        const float w3a = Wg[(lane+96)*3+0], w3b = Wg[(lane+96)*3+1], w3c = Wg[(lane+96)*3+2];
        for (int rr = 0; rr < 16; rr++) {
            const int r = base + w*16 + rr;
            const float* __restrict__ xr = x + r * ND;
            float x0 = xr[lane], x1 = xr[lane+32], x2 = xr[lane+64], x3 = xr[lane+96];
            float s0 = x0*w0a + x1*w1a + x2*w2a + x3*w3a;
            float s1 = x0*w0b + x1*w1b + x2*w2b + x3*w3b;
            float s2 = x0*w0c + x1*w1c + x2*w2c + x3*w3c;
            #pragma unroll
            for (int o = 16; o; o >>= 1) {
                s0 += __shfl_xor_sync(0xffffffffu, s0, o);
                s1 += __shfl_xor_sync(0xffffffffu, s1, o);
                s2 += __shfl_xor_sync(0xffffffffu, s2, o);
            }
            if (lane == 0) {
                float om = 1.f / (1.f + expf(s0 + b0));       // 1 - sigmoid
                float e  = 1.f / (1.f + expf(-(s1 + b1)));
                float th = 1.f / (1.f + expf(-(s2 + b2)));
                g_g4[r] = make_float4(om, e, th, 0.f);
            }
        }
        return;
    }
    extern __shared__ __nv_bfloat16 bsm[];
    __nv_bfloat16* __restrict__ XH  = bsm;              // 128*KP
    __nv_bfloat16* __restrict__ XL  = XH  + 128*KP;
    __nv_bfloat16* __restrict__ WTH = XL  + 128*KP;     // transposed W: [n][k]
    __nv_bfloat16* __restrict__ WTL = WTH + 128*KP;

    const float* __restrict__ W = (which == 0) ? Wk : ((which == 1) ? Wv : Wq);
    float* __restrict__ out = (which == 0) ? g_k : ((which == 1) ? g_v : g_q);
    const int rowBase = blockIdx.x * 128;

    const int tid  = threadIdx.x;
    const int lane = tid & 31;
    const int warp = tid >> 5;
    const int g    = lane >> 2;
    const int tig  = lane & 3;
    const int wm   = warp >> 1;
    const int wn   = warp & 1;

    float acc[2][8][4];
    #pragma unroll
    for (int mt = 0; mt < 2; mt++)
        #pragma unroll
        for (int nt = 0; nt < 8; nt++)
            #pragma unroll
            for (int r = 0; r < 4; r++) acc[mt][nt][r] = 0.f;

    for (int k0 = 0; k0 < 128; k0 += 64) {
        {
            const int row = tid >> 1, half = tid & 1;
            const float* __restrict__ src = x + (rowBase + row)*ND + k0 + half*32;
            __nv_bfloat16* __restrict__ dh = XH + row*KP + half*32;
            __nv_bfloat16* __restrict__ dl = XL + row*KP + half*32;
            #pragma unroll
            for (int j = 0; j < 8; j++) {
                float4 v = *reinterpret_cast<const float4*>(&src[j*4]);
                #pragma unroll
                for (int i = 0; i < 4; i++) {
                    __nv_bfloat16 h, l;
                    bf16split((&v.x)[i], h, l);
                    dh[j*4+i] = h; dl[j*4+i] = l;
                }
            }
        }
        {
            const int krow = tid >> 2, nb = (tid & 3)*32;
            const float* __restrict__ src = W + (k0 + krow)*ND + nb;
            #pragma unroll
            for (int j = 0; j < 8; j++) {
                float4 v = *reinterpret_cast<const float4*>(&src[j*4]);
                #pragma unroll
                for (int i = 0; i < 4; i++) {
                    __nv_bfloat16 h, l;
                    bf16split((&v.x)[i], h, l);
                    const int n = nb + j*4 + i;
                    WTH[n*KP + krow] = h;
                    WTL[n*KP + krow] = l;
                }
            }
        }
        __syncthreads();

        #pragma unroll
        for (int kk = 0; kk < 64; kk += 16) {
            unsigned ah[2][4], al[2][4];
            #pragma unroll
            for (int mt = 0; mt < 2; mt++) {
                const int r0 = (wm*32 + mt*16 + g)*KP + kk + tig*2;
                const int r1 = r0 + 8*KP;
                ah[mt][0] = *reinterpret_cast<const unsigned*>(&XH[r0]);
                ah[mt][1] = *reinterpret_cast<const unsigned*>(&XH[r1]);
                ah[mt][2] = *reinterpret_cast<const unsigned*>(&XH[r0 + 8]);
                ah[mt][3] = *reinterpret_cast<const unsigned*>(&XH[r1 + 8]);
                al[mt][0] = *reinterpret_cast<const unsigned*>(&XL[r0]);
                al[mt][1] = *reinterpret_cast<const unsigned*>(&XL[r1]);
                al[mt][2] = *reinterpret_cast<const unsigned*>(&XL[r0 + 8]);
                al[mt][3] = *reinterpret_cast<const unsigned*>(&XL[r1 + 8]);
            }
            #pragma unroll
            for (int nt = 0; nt < 8; nt++) {
                const int bo = (wn*64 + nt*8 + g)*KP + kk + tig*2;
                unsigned bh[2], bl[2];
                bh[0] = *reinterpret_cast<const unsigned*>(&WTH[bo]);
                bh[1] = *reinterpret_cast<const unsigned*>(&WTH[bo + 8]);
                bl[0] = *reinterpret_cast<const unsigned*>(&WTL[bo]);
                bl[1] = *reinterpret_cast<const unsigned*>(&WTL[bo + 8]);
                #pragma unroll
                for (int mt = 0; mt < 2; mt++) {
                    mma16816(acc[mt][nt], ah[mt], bh);
                    mma16816(acc[mt][nt], ah[mt], bl);
                    mma16816(acc[mt][nt], al[mt], bh);
                }
            }
        }
        __syncthreads();
    }

    #pragma unroll
    for (int mt = 0; mt < 2; mt++) {
        const int r0 = rowBase + wm*32 + mt*16 + g;
        const int r1 = r0 + 8;
        #pragma unroll
        for (int nt = 0; nt < 8; nt++) {
            const int c0 = wn*64 + nt*8 + tig*2;
            *reinterpret_cast<float2*>(&out[r0*ND + c0]) = make_float2(acc[mt][nt][0], acc[mt][nt][1]);
            *reinterpret_cast<float2*>(&out[r1*ND + c0]) = make_float2(acc[mt][nt][2], acc[mt][nt][3]);
        }
    }
}

// ============================================================
// Pass 1: chunk map composition (diag maps + weight maps)
// ============================================================
__global__ __launch_bounds__(128) void pass1_kernel()
{
    const int blk = blockIdx.x;
    if (blk < NB*NC) {
        const int b = blk >> 4, c = blk & (NC-1);
        const int i = threadIdx.x;
        const int t0 = c * LC;
        const float*  __restrict__ kp = g_k + (b*NS + t0)*ND + i;
        const float*  __restrict__ vp = g_v + (b*NS + t0)*ND + i;
        const float4* __restrict__ gp = g_g4 + b*NS + t0;

        float m00=1.f, m01=0.f, m10=0.f, m11=1.f, w0=0.f, w1=0.f;
        float kA[UG], vA[UG], kB[UG], vB[UG];
        float4 gA[UG], gB[UG];
        #pragma unroll
        for (int s = 0; s < UG; s++) { kA[s]=kp[s*ND]; vA[s]=vp[s*ND]; gA[s]=gp[s]; }

        #pragma unroll
        for (int g = 0; g < NGRP; g++) {
            const bool useA = ((g & 1) == 0);
            if (g + 1 < NGRP) {
                #pragma unroll
                for (int s = 0; s < UG; s++) {
                    int off = ((g+1)*UG + s)*ND;
                    int go  = (g+1)*UG + s;
                    if (useA) { kB[s]=kp[off]; vB[s]=vp[off]; gB[s]=gp[go]; }
                    else      { kA[s]=kp[off]; vA[s]=vp[off]; gA[s]=gp[go]; }
                }
            }
            #pragma unroll
            for (int s = 0; s < UG; s++) {
                float  kk = useA ? kA[s] : kB[s];
                float  vv = useA ? vA[s] : vB[s];
                float4 gg = useA ? gA[s] : gB[s];
                float om = gg.x, e = gg.y, th = gg.z;
                float t1 = th*kk, c2 = t1*vv, d0 = -t1*kk, a00 = om + d0;
                float te0 = e*m10, te1 = e*m11;
                float n00 = fmaf(a00, m00, te0), n10 = fmaf(d0, m00, te0);
                float n01 = fmaf(a00, m01, te1), n11 = fmaf(d0, m01, te1);
                float tev = fmaf(e, w1, c2);
                float nw0 = fmaf(a00, w0, tev), nw1 = fmaf(d0, w0, tev);
                m00=n00; m01=n01; m10=n10; m11=n11; w0=nw0; w1=nw1;
            }
        }
        const int base = (b*NC + c)*ND + i;
        const int ST = NB*NC*ND;
        g_dmap[0*ST+base] = m00; g_dmap[1*ST+base] = m01;
        g_dmap[2*ST+base] = m10; g_dmap[3*ST+base] = m11;
        g_dmap[4*ST+base] = w0;  g_dmap[5*ST+base] = w1;
    } else {
        const int u = threadIdx.x;
        const int b = u >> 4, wc = u & (NC-1);
        const float4* __restrict__ gp = g_g4 + b*NS + wc*LC;
        float ph = 1.f, qh = 1.f, gh = 0.f;
        #pragma unroll 4
        for (int s = LC-1; s >= 0; s--) {
            float4 g = gp[s];
            float p = g.x, q = g.y;
            gh = fmaf(q, gh, p*ph);
            ph *= p;
            qh *= q;
        }
        g_wmap[0*NB*NC + u] = ph;
        g_wmap[1*NB*NC + u] = qh;
        g_wmap[2*NB*NC + u] = gh;
    }
}

// ============================================================
// Pass 2: sequential combine over chunk maps -> chunk-entry states
// ============================================================
__global__ __launch_bounds__(128) void pass2_kernel()
{
    if (blockIdx.x < NB) {
        const int b = blockIdx.x, d = threadIdx.x;
        const int ST = NB*NC*ND;
        float pm[16][6];
        #pragma unroll
        for (int c = 0; c < NC; c++) {
            const int idx = (b*NC + c)*ND + d;
            #pragma unroll
            for (int j = 0; j < 6; j++) pm[c][j] = g_dmap[j*ST + idx];
        }
        float s0 = 0.f, s1 = 0.f;
        #pragma unroll
        for (int c = 0; c < NC; c++) {
            const int idx = (b*NC + c)*ND + d;
            g_dinit0[idx] = s0; g_dinit1[idx] = s1;
            float ns0 = fmaf(pm[c][0], s0, fmaf(pm[c][1], s1, pm[c][4]));
            float ns1 = fmaf(pm[c][2], s0, fmaf(pm[c][3], s1, pm[c][5]));
            s0 = ns0; s1 = ns1;
        }
    } else if (threadIdx.x < NB) {
        const int b = threadIdx.x;
        float ph[16], qh[16], gh[16];
        #pragma unroll
        for (int wc = 0; wc < NC; wc++) {
            const int u = b*NC + wc;
            ph[wc] = g_wmap[0*NB*NC + u];
            qh[wc] = g_wmap[1*NB*NC + u];
            gh[wc] = g_wmap[2*NB*NC + u];
        }
        float P = 1.f, E = 1.f, w = 1.f;
        #pragma unroll
        for (int wc = NC-1; wc >= 0; wc--) {
            const int u = b*NC + wc;
            g_winit[u*3+0] = P; g_winit[u*3+1] = E; g_winit[u*3+2] = w;
            float nw = fmaf(qh[wc], w, gh[wc]*P);
            P *= ph[wc]; E *= qh[wc]; w = nw;
        }
    }
}

// ============================================================
// Fused pass 3: per (b,chunk) block, 512 threads
//  phase A: tid<128 diag replay (y -> d_out, k/err fp32 -> smem);
//           tid==128 backward weight scan -> sA/sB
//  phase B: convert+weight+transpose: KA/KB (weighted k) and ET (err)
//           as bf16 hi/lo [i][s] with KP padding
//  phase C: warps 0-7 -> A-weighted (M) partial, warps 8-15 -> B-weighted (S)
//           via m16n8k16 bf16 3-term split mma
// ============================================================
__global__ __launch_bounds__(512) void fused3_kernel(float* __restrict__ d_out)
{
    extern __shared__ char smc[];
    float* __restrict__ Kraw = reinterpret_cast<float*>(smc);       // [LC][ND]
    float* __restrict__ Eraw = Kraw + LC*ND;                        // [LC][ND]
    __nv_bfloat16* __restrict__ KAh = reinterpret_cast<__nv_bfloat16*>(Eraw + LC*ND);
    __nv_bfloat16* __restrict__ KAl = KAh + ND*KP;
    __nv_bfloat16* __restrict__ KBh = KAl + ND*KP;
    __nv_bfloat16* __restrict__ KBl = KBh + ND*KP;
    __nv_bfloat16* __restrict__ ETh = KBl + ND*KP;
    __nv_bfloat16* __restrict__ ETl = ETh + ND*KP;
    float* __restrict__ sA = reinterpret_cast<float*>(ETl + ND*KP);
    float* __restrict__ sB = sA + LC;

    const int b = blockIdx.x >> 4, c = blockIdx.x & (NC-1);
    const int t0 = c * LC;
    const int tid = threadIdx.x;

    if (tid == 128) {
        const int u = b*NC + c;
        const float4* __restrict__ gp = g_g4 + b*NS + t0;
        float P = g_winit[u*3+0], E = g_winit[u*3+1], w = g_winit[u*3+2];
        #pragma unroll 4
        for (int s = LC-1; s >= 0; s--) {
            float4 g = gp[s];
            float th = g.z;
            sA[s] = -th * w;
            sB[s] = -th * E;
            P *= g.x;
            E *= g.y;
            w  = fmaf(g.y, w, P);
        }
    }
    if (tid < 128) {
        const int i = tid;
        const float*  __restrict__ kp = g_k + (b*NS + t0)*ND + i;
        const float*  __restrict__ vp = g_v + (b*NS + t0)*ND + i;
        const float*  __restrict__ qp = g_q + (b*NS + t0)*ND + i;
        const float4* __restrict__ gp = g_g4 + b*NS + t0;
        float* __restrict__ op = d_out + (b*NS + t0)*ND + i;

        const int ii = (b*NC + c)*ND + i;
        float dm = g_dinit0[ii], ds = g_dinit1[ii];

        float kA[UG], vA[UG], qA[UG], kB[UG], vB[UG], qB[UG];
        float4 gA[UG], gB[UG];
        #pragma unroll
        for (int s = 0; s < UG; s++) { kA[s]=kp[s*ND]; vA[s]=vp[s*ND]; qA[s]=qp[s*ND]; gA[s]=gp[s]; }

        #pragma unroll
        for (int g = 0; g < NGRP; g++) {
            const bool useA = ((g & 1) == 0);
            if (g + 1 < NGRP) {
                #pragma unroll
                for (int s = 0; s < UG; s++) {
                    int off = ((g+1)*UG + s)*ND;
                    int go  = (g+1)*UG + s;
                    if (useA) { kB[s]=kp[off]; vB[s]=vp[off]; qB[s]=qp[off]; gB[s]=gp[go]; }
                    else      { kA[s]=kp[off]; vA[s]=vp[off]; qA[s]=qp[off]; gA[s]=gp[go]; }
                }
            }
            #pragma unroll
            for (int s = 0; s < UG; s++) {
                float  kk = useA ? kA[s] : kB[s];
                float  vv = useA ? vA[s] : vB[s];
                float  qq = useA ? qA[s] : qB[s];
                float4 gg = useA ? gA[s] : gB[s];
                float om = gg.x, e = gg.y, th = gg.z;
                const int st = g*UG + s;
                op[st*ND] = qq * dm;
                float err = fmaf(kk, dm, -vv);
                Kraw[st*ND + i] = kk;
                Eraw[st*ND + i] = err;
                float t1 = th*kk, c2 = t1*vv, d0 = -t1*kk;
                float inner = fmaf(e, ds, c2);
                ds = fmaf(d0, dm, inner);
                dm = fmaf(om, dm, ds);
            }
        }
    }
    __syncthreads();

    // ---- phase B: convert + weight + transpose ----
    #pragma unroll
    for (int r = 0; r < 16; r++) {
        const int idx = tid + r*512;        // = s*ND + i
        const int s = idx >> 7, i = idx & 127;
        const float kf = Kraw[idx];
        const float ef = Eraw[idx];
        const float pa = sA[s] * kf;
        const float pb = sB[s] * kf;
        __nv_bfloat16 h, l;
        bf16split(pa, h, l); KAh[i*KP + s] = h; KAl[i*KP + s] = l;
        bf16split(pb, h, l); KBh[i*KP + s] = h; KBl[i*KP + s] = l;
        bf16split(ef, h, l); ETh[i*KP + s] = h; ETl[i*KP + s] = l;
    }
    __syncthreads();

    // ---- phase C: tensor-core weighted outer products ----
    const int which = tid >> 8;
    const int t256 = tid & 255;
    const int lane = t256 & 31, warp = t256 >> 5;
    const int g = lane >> 2, tig = lane & 3;
    const int wm = warp >> 1, wn = warp & 1;
    const __nv_bfloat16* __restrict__ Ah = which ? KBh : KAh;
    const __nv_bfloat16* __restrict__ Al = which ? KBl : KAl;

    float acc[2][8][4];
    #pragma unroll
    for (int mt = 0; mt < 2; mt++)
        #pragma unroll
        for (int nt = 0; nt < 8; nt++)
            #pragma unroll
            for (int r = 0; r < 4; r++) acc[mt][nt][r] = 0.f;

    #pragma unroll
    for (int kk = 0; kk < LC; kk += 16) {
        unsigned ah[2][4], al[2][4];
        #pragma unroll
        for (int mt = 0; mt < 2; mt++) {
            const int r0 = (wm*32 + mt*16 + g)*KP + kk + tig*2;
            const int r1 = r0 + 8*KP;
            ah[mt][0] = *reinterpret_cast<const unsigned*>(&Ah[r0]);
            ah[mt][1] = *reinterpret_cast<const unsigned*>(&Ah[r1]);
            ah[mt][2] = *reinterpret_cast<const unsigned*>(&Ah[r0 + 8]);
            ah[mt][3] = *reinterpret_cast<const unsigned*>(&Ah[r1 + 8]);
            al[mt][0] = *reinterpret_cast<const unsigned*>(&Al[r0]);
            al[mt][1] = *reinterpret_cast<const unsigned*>(&Al[r1]);
            al[mt][2] = *reinterpret_cast<const unsigned*>(&Al[r0 + 8]);
            al[mt][3] = *reinterpret_cast<const unsigned*>(&Al[r1 + 8]);
        }
        #pragma unroll
        for (int nt = 0; nt < 8; nt++) {
            const int bo = (wn*64 + nt*8 + g)*KP + kk + tig*2;
            unsigned bh[2], bl[2];
            bh[0] = *reinterpret_cast<const unsigned*>(&ETh[bo]);
            bh[1] = *reinterpret_cast<const unsigned*>(&ETh[bo + 8]);
            bl[0] = *reinterpret_cast<const unsigned*>(&ETl[bo]);
            bl[1] = *reinterpret_cast<const unsigned*>(&ETl[bo + 8]);
            #pragma unroll
            for (int mt = 0; mt < 2; mt++) {
                mma16816(acc[mt][nt], ah[mt], bh);
                mma16816(acc[mt][nt], ah[mt], bl);
                mma16816(acc[mt][nt], al[mt], bh);
            }
        }
    }

    float* __restrict__ C = g_part + ((b*2 + which)*NC + c)*ND*ND;
    #pragma unroll
    for (int mt = 0; mt < 2; mt++) {
        const int r0 = wm*32 + mt*16 + g;
        const int r1 = r0 + 8;
        #pragma unroll
        for (int nt = 0; nt < 8; nt++) {
            const int c0 = wn*64 + nt*8 + tig*2;
            *reinterpret_cast<float2*>(&C[r0*ND + c0]) = make_float2(acc[mt][nt][0], acc[mt][nt][1]);
            *reinterpret_cast<float2*>(&C[r1*ND + c0]) = make_float2(acc[mt][nt][2], acc[mt][nt][3]);
        }
    }
}

// ============================================================
// Kernel 5: reduce split partials -> d_out tail (float4)
// ============================================================
__global__ __launch_bounds__(256) void reduce_kernel(float* __restrict__ d_out)
{
    const int g4 = blockIdx.x * 256 + threadIdx.x;   // [0, 65536) float4 units
    const int gid = g4 * 4;
    const int which = gid >> 17;
    const int r  = gid & 131071;
    const int b  = r >> 14;
    const int ij = r & 16383;
    const float* __restrict__ p = g_part + ((b*2 + which)*NC)*ND*ND + ij;
    float4 s = make_float4(0.f, 0.f, 0.f, 0.f);
    #pragma unroll
    for (int sp = 0; sp < NC; sp++) {
        float4 v = *reinterpret_cast<const float4*>(&p[sp*ND*ND]);
        s.x += v.x; s.y += v.y; s.z += v.z; s.w += v.w;
    }
    *reinterpret_cast<float4*>(&d_out[BSD + gid]) = s;
}

// ============================================================
extern "C" void kernel_launch(void* const* d_in, const int* in_sizes, int n_in,
                              void* d_out, int out_size)
{
    const float* x  = (const float*)d_in[0];
    const float* Wk = (const float*)d_in[1];
    const float* Wv = (const float*)d_in[2];
    const float* Wq = (const float*)d_in[3];
    const float* Wg = (const float*)d_in[4];
    const float* bg = (const float*)d_in[5];
    float* out = (float*)d_out;

    const int k1_smem = 4 * 128 * KP * (int)sizeof(__nv_bfloat16);  // 73728 B
    const int fused_smem = 2*LC*ND*(int)sizeof(float)               // Kraw/Eraw
                         + 6*ND*KP*(int)sizeof(__nv_bfloat16)       // bf16 tiles
                         + 2*LC*(int)sizeof(float);                 // sA/sB = 176640 B
    cudaFuncSetAttribute(k1_qkv_gates, cudaFuncAttributeMaxDynamicSharedMemorySize, k1_smem);
    cudaFuncSetAttribute(fused3_kernel, cudaFuncAttributeMaxDynamicSharedMemorySize, fused_smem);

    k1_qkv_gates<<<dim3(64, 4), 256, k1_smem>>>(x, Wk, Wv, Wq, Wg, bg);
    pass1_kernel<<<NB*NC + 1, 128>>>();
    pass2_kernel<<<NB + 1, 128>>>();
    fused3_kernel<<<NB*NC, 512, fused_smem>>>(out);
    reduce_kernel<<<256, 256>>>(out);
}

// round 7
// speedup vs baseline: 5.7253x; 1.0112x over previous
#include <cuda_runtime.h>
#include <cuda_bf16.h>

#define NB 8
#define NS 1024
#define ND 128
#define NROWS (NB*NS)   // 8192
#define BSD (NB*NS*ND)  // 1048576

#define NC 16           // coarse chunks (GEMM splits)
#define LC 64           // steps per coarse chunk
#define LF 16           // steps per fine sub-chunk (replay granularity)
#define UG 8            // prefetch group size (pass1)
#define NGRP (LC/UG)

#define KP 72           // padded bf16 k-stride in smem (conflict-free frag loads)

// ---- scratch (static device globals; no runtime allocation) ----
__device__ float  g_k[NROWS*ND];
__device__ float  g_v[NROWS*ND];
__device__ float  g_q[NROWS*ND];
__device__ float4 g_g4[NROWS];           // (om=1-a, e, th, 0) per (b,t)
__device__ float  g_dmap[6*NB*NC*ND];    // composed coarse diag maps
__device__ float  g_dinit0[NB*NC*ND];
__device__ float  g_dinit1[NB*NC*ND];
__device__ float  g_wmap[3*NB*NC];
__device__ float  g_winit[NB*NC*3];
__device__ float  g_part[NB*2*NC*ND*ND];

// ---- mma.sync m16n8k16 bf16 -> f32 ----
__device__ __forceinline__ void mma16816(float* c, const unsigned* a, const unsigned* b)
{
    asm volatile(
        "mma.sync.aligned.m16n8k16.row.col.f32.bf16.bf16.f32 "
        "{%0,%1,%2,%3}, {%4,%5,%6,%7}, {%8,%9}, {%0,%1,%2,%3};"
        : "+f"(c[0]), "+f"(c[1]), "+f"(c[2]), "+f"(c[3])
        : "r"(a[0]), "r"(a[1]), "r"(a[2]), "r"(a[3]), "r"(b[0]), "r"(b[1]));
}

__device__ __forceinline__ void bf16split(float f, __nv_bfloat16& h, __nv_bfloat16& l)
{
    h = __float2bfloat16_rn(f);
    l = __float2bfloat16_rn(f - __bfloat162float(h));
}

// ============================================================
// Kernel 1: y<3: k/v/q = x@W via bf16-split tensor mma; y==3: gates
// ============================================================
__global__ __launch_bounds__(256) void k1_qkv_gates(
    const float* __restrict__ x, const float* __restrict__ Wk,
    const float* __restrict__ Wv, const float* __restrict__ Wq,
    const float* __restrict__ Wg, const float* __restrict__ bg)
{
    const int which = blockIdx.y;
    if (which == 3) {
        const int base = blockIdx.x * 128;
        const int w = threadIdx.x >> 5, lane = threadIdx.x & 31;
        const float b0 = bg[0], b1 = bg[1], b2 = bg[2];
        const float w0a = Wg[lane*3+0],      w0b = Wg[lane*3+1],      w0c = Wg[lane*3+2];
        const float w1a = Wg[(lane+32)*3+0], w1b = Wg[(lane+32)*3+1], w1c = Wg[(lane+32)*3+2];
        const float w2a = Wg[(lane+64)*3+0], w2b = Wg[(lane+64)*3+1], w2c = Wg[(lane+64)*3+2];
        const float w3a = Wg[(lane+96)*3+0], w3b = Wg[(lane+96)*3+1], w3c = Wg[(lane+96)*3+2];
        for (int rr = 0; rr < 16; rr++) {
            const int r = base + w*16 + rr;
            const float* __restrict__ xr = x + r * ND;
            float x0 = xr[lane], x1 = xr[lane+32], x2 = xr[lane+64], x3 = xr[lane+96];
            float s0 = x0*w0a + x1*w1a + x2*w2a + x3*w3a;
            float s1 = x0*w0b + x1*w1b + x2*w2b + x3*w3b;
            float s2 = x0*w0c + x1*w1c + x2*w2c + x3*w3c;
            #pragma unroll
            for (int o = 16; o; o >>= 1) {
                s0 += __shfl_xor_sync(0xffffffffu, s0, o);
                s1 += __shfl_xor_sync(0xffffffffu, s1, o);
                s2 += __shfl_xor_sync(0xffffffffu, s2, o);
            }
            if (lane == 0) {
                float om = 1.f / (1.f + expf(s0 + b0));       // 1 - sigmoid
                float e  = 1.f / (1.f + expf(-(s1 + b1)));
                float th = 1.f / (1.f + expf(-(s2 + b2)));
                g_g4[r] = make_float4(om, e, th, 0.f);
            }
        }
        return;
    }
    extern __shared__ __nv_bfloat16 bsm[];
    __nv_bfloat16* __restrict__ XH  = bsm;
    __nv_bfloat16* __restrict__ XL  = XH  + 128*KP;
    __nv_bfloat16* __restrict__ WTH = XL  + 128*KP;
    __nv_bfloat16* __restrict__ WTL = WTH + 128*KP;

    const float* __restrict__ W = (which == 0) ? Wk : ((which == 1) ? Wv : Wq);
    float* __restrict__ out = (which == 0) ? g_k : ((which == 1) ? g_v : g_q);
    const int rowBase = blockIdx.x * 128;

    const int tid  = threadIdx.x;
    const int lane = tid & 31;
    const int warp = tid >> 5;
    const int g    = lane >> 2;
    const int tig  = lane & 3;
    const int wm   = warp >> 1;
    const int wn   = warp & 1;

    float acc[2][8][4];
    #pragma unroll
    for (int mt = 0; mt < 2; mt++)
        #pragma unroll
        for (int nt = 0; nt < 8; nt++)
            #pragma unroll
            for (int r = 0; r < 4; r++) acc[mt][nt][r] = 0.f;

    for (int k0 = 0; k0 < 128; k0 += 64) {
        {
            const int row = tid >> 1, half = tid & 1;
            const float* __restrict__ src = x + (rowBase + row)*ND + k0 + half*32;
            __nv_bfloat16* __restrict__ dh = XH + row*KP + half*32;
            __nv_bfloat16* __restrict__ dl = XL + row*KP + half*32;
            #pragma unroll
            for (int j = 0; j < 8; j++) {
                float4 v = *reinterpret_cast<const float4*>(&src[j*4]);
                #pragma unroll
                for (int i = 0; i < 4; i++) {
                    __nv_bfloat16 h, l;
                    bf16split((&v.x)[i], h, l);
                    dh[j*4+i] = h; dl[j*4+i] = l;
                }
            }
        }
        {
            const int krow = tid >> 2, nb = (tid & 3)*32;
            const float* __restrict__ src = W + (k0 + krow)*ND + nb;
            #pragma unroll
            for (int j = 0; j < 8; j++) {
                float4 v = *reinterpret_cast<const float4*>(&src[j*4]);
                #pragma unroll
                for (int i = 0; i < 4; i++) {
                    __nv_bfloat16 h, l;
                    bf16split((&v.x)[i], h, l);
                    const int n = nb + j*4 + i;
                    WTH[n*KP + krow] = h;
                    WTL[n*KP + krow] = l;
                }
            }
        }
        __syncthreads();

        #pragma unroll
        for (int kk = 0; kk < 64; kk += 16) {
            unsigned ah[2][4], al[2][4];
            #pragma unroll
            for (int mt = 0; mt < 2; mt++) {
                const int r0 = (wm*32 + mt*16 + g)*KP + kk + tig*2;
                const int r1 = r0 + 8*KP;
                ah[mt][0] = *reinterpret_cast<const unsigned*>(&XH[r0]);
                ah[mt][1] = *reinterpret_cast<const unsigned*>(&XH[r1]);
                ah[mt][2] = *reinterpret_cast<const unsigned*>(&XH[r0 + 8]);
                ah[mt][3] = *reinterpret_cast<const unsigned*>(&XH[r1 + 8]);
                al[mt][0] = *reinterpret_cast<const unsigned*>(&XL[r0]);
                al[mt][1] = *reinterpret_cast<const unsigned*>(&XL[r1]);
                al[mt][2] = *reinterpret_cast<const unsigned*>(&XL[r0 + 8]);
                al[mt][3] = *reinterpret_cast<const unsigned*>(&XL[r1 + 8]);
            }
            #pragma unroll
            for (int nt = 0; nt < 8; nt++) {
                const int bo = (wn*64 + nt*8 + g)*KP + kk + tig*2;
                unsigned bh[2], bl[2];
                bh[0] = *reinterpret_cast<const unsigned*>(&WTH[bo]);
                bh[1] = *reinterpret_cast<const unsigned*>(&WTH[bo + 8]);
                bl[0] = *reinterpret_cast<const unsigned*>(&WTL[bo]);
                bl[1] = *reinterpret_cast<const unsigned*>(&WTL[bo + 8]);
                #pragma unroll
                for (int mt = 0; mt < 2; mt++) {
                    mma16816(acc[mt][nt], ah[mt], bh);
                    mma16816(acc[mt][nt], ah[mt], bl);
                    mma16816(acc[mt][nt], al[mt], bh);
                }
            }
        }
        __syncthreads();
    }

    #pragma unroll
    for (int mt = 0; mt < 2; mt++) {
        const int r0 = rowBase + wm*32 + mt*16 + g;
        const int r1 = r0 + 8;
        #pragma unroll
        for (int nt = 0; nt < 8; nt++) {
            const int c0 = wn*64 + nt*8 + tig*2;
            *reinterpret_cast<float2*>(&out[r0*ND + c0]) = make_float2(acc[mt][nt][0], acc[mt][nt][1]);
            *reinterpret_cast<float2*>(&out[r1*ND + c0]) = make_float2(acc[mt][nt][2], acc[mt][nt][3]);
        }
    }
}

// ============================================================
// Pass 1: coarse chunk map composition (diag maps + weight maps)
// ============================================================
__global__ __launch_bounds__(128) void pass1_kernel()
{
    const int blk = blockIdx.x;
    if (blk < NB*NC) {
        const int b = blk >> 4, c = blk & (NC-1);
        const int i = threadIdx.x;
        const int t0 = c * LC;
        const float*  __restrict__ kp = g_k + (b*NS + t0)*ND + i;
        const float*  __restrict__ vp = g_v + (b*NS + t0)*ND + i;
        const float4* __restrict__ gp = g_g4 + b*NS + t0;

        float m00=1.f, m01=0.f, m10=0.f, m11=1.f, w0=0.f, w1=0.f;
        float kA[UG], vA[UG], kB[UG], vB[UG];
        float4 gA[UG], gB[UG];
        #pragma unroll
        for (int s = 0; s < UG; s++) { kA[s]=kp[s*ND]; vA[s]=vp[s*ND]; gA[s]=gp[s]; }

        #pragma unroll
        for (int g = 0; g < NGRP; g++) {
            const bool useA = ((g & 1) == 0);
            if (g + 1 < NGRP) {
                #pragma unroll
                for (int s = 0; s < UG; s++) {
                    int off = ((g+1)*UG + s)*ND;
                    int go  = (g+1)*UG + s;
                    if (useA) { kB[s]=kp[off]; vB[s]=vp[off]; gB[s]=gp[go]; }
                    else      { kA[s]=kp[off]; vA[s]=vp[off]; gA[s]=gp[go]; }
                }
            }
            #pragma unroll
            for (int s = 0; s < UG; s++) {
                float  kk = useA ? kA[s] : kB[s];
                float  vv = useA ? vA[s] : vB[s];
                float4 gg = useA ? gA[s] : gB[s];
                float om = gg.x, e = gg.y, th = gg.z;
                float t1 = th*kk, c2 = t1*vv, d0 = -t1*kk, a00 = om + d0;
                float te0 = e*m10, te1 = e*m11;
                float n00 = fmaf(a00, m00, te0), n10 = fmaf(d0, m00, te0);
                float n01 = fmaf(a00, m01, te1), n11 = fmaf(d0, m01, te1);
                float tev = fmaf(e, w1, c2);
                float nw0 = fmaf(a00, w0, tev), nw1 = fmaf(d0, w0, tev);
                m00=n00; m01=n01; m10=n10; m11=n11; w0=nw0; w1=nw1;
            }
        }
        const int base = (b*NC + c)*ND + i;
        const int ST = NB*NC*ND;
        g_dmap[0*ST+base] = m00; g_dmap[1*ST+base] = m01;
        g_dmap[2*ST+base] = m10; g_dmap[3*ST+base] = m11;
        g_dmap[4*ST+base] = w0;  g_dmap[5*ST+base] = w1;
    } else {
        const int u = threadIdx.x;
        const int b = u >> 4, wc = u & (NC-1);
        const float4* __restrict__ gp = g_g4 + b*NS + wc*LC;
        float ph = 1.f, qh = 1.f, gh = 0.f;
        #pragma unroll 4
        for (int s = LC-1; s >= 0; s--) {
            float4 g = gp[s];
            float p = g.x, q = g.y;
            gh = fmaf(q, gh, p*ph);
            ph *= p;
            qh *= q;
        }
        g_wmap[0*NB*NC + u] = ph;
        g_wmap[1*NB*NC + u] = qh;
        g_wmap[2*NB*NC + u] = gh;
    }
}

// ============================================================
// Pass 2: sequential combine over coarse maps -> coarse entry states
// ============================================================
__global__ __launch_bounds__(128) void pass2_kernel()
{
    if (blockIdx.x < NB) {
        const int b = blockIdx.x, d = threadIdx.x;
        const int ST = NB*NC*ND;
        float pm[16][6];
        #pragma unroll
        for (int c = 0; c < NC; c++) {
            const int idx = (b*NC + c)*ND + d;
            #pragma unroll
            for (int j = 0; j < 6; j++) pm[c][j] = g_dmap[j*ST + idx];
        }
        float s0 = 0.f, s1 = 0.f;
        #pragma unroll
        for (int c = 0; c < NC; c++) {
            const int idx = (b*NC + c)*ND + d;
            g_dinit0[idx] = s0; g_dinit1[idx] = s1;
            float ns0 = fmaf(pm[c][0], s0, fmaf(pm[c][1], s1, pm[c][4]));
            float ns1 = fmaf(pm[c][2], s0, fmaf(pm[c][3], s1, pm[c][5]));
            s0 = ns0; s1 = ns1;
        }
    } else if (threadIdx.x < NB) {
        const int b = threadIdx.x;
        float ph[16], qh[16], gh[16];
        #pragma unroll
        for (int wc = 0; wc < NC; wc++) {
            const int u = b*NC + wc;
            ph[wc] = g_wmap[0*NB*NC + u];
            qh[wc] = g_wmap[1*NB*NC + u];
            gh[wc] = g_wmap[2*NB*NC + u];
        }
        float P = 1.f, E = 1.f, w = 1.f;
        #pragma unroll
        for (int wc = NC-1; wc >= 0; wc--) {
            const int u = b*NC + wc;
            g_winit[u*3+0] = P; g_winit[u*3+1] = E; g_winit[u*3+2] = w;
            float nw = fmaf(qh[wc], w, gh[wc]*P);
            P *= ph[wc]; E *= qh[wc]; w = nw;
        }
    }
}

// ============================================================
// Fused pass 3: per (b, coarse chunk) block, 512 threads
//  A0: all threads — thread (sub,i) composes its 16-step fine diag map -> smem;
//      i==0 threads compose fine weight maps
//  combine: each thread derives its sub-chunk entry state (<=3 smem map applies);
//      i==0 threads derive weight entries and do 16-step backward scans -> sA/sB
//  A1: all threads replay 16 steps (y -> d_out, k/err fp32 -> smem)
//  B:  convert+weight+transpose to bf16 hi/lo [i][s]
//  C:  warps 0-7 A-weighted (M) partial, warps 8-15 B-weighted (S) via mma
// ============================================================
__global__ __launch_bounds__(512) void fused3_kernel(float* __restrict__ d_out)
{
    extern __shared__ char smc[];
    float* __restrict__ Kraw = reinterpret_cast<float*>(smc);       // [LC][ND]
    float* __restrict__ Eraw = Kraw + LC*ND;                        // [LC][ND]
    float* __restrict__ fm   = Eraw + LC*ND;                        // [6][4][128]
    float* __restrict__ sA   = fm + 6*4*128;                        // [LC]
    float* __restrict__ sB   = sA + LC;                             // [LC]
    float* __restrict__ wfm  = sB + LC;                             // [4][3] (+pad)
    __nv_bfloat16* __restrict__ KAh = reinterpret_cast<__nv_bfloat16*>(wfm + 16);
    __nv_bfloat16* __restrict__ KAl = KAh + ND*KP;
    __nv_bfloat16* __restrict__ KBh = KAl + ND*KP;
    __nv_bfloat16* __restrict__ KBl = KBh + ND*KP;
    __nv_bfloat16* __restrict__ ETh = KBl + ND*KP;
    __nv_bfloat16* __restrict__ ETl = ETh + ND*KP;

    const int b = blockIdx.x >> 4, c = blockIdx.x & (NC-1);
    const int tid = threadIdx.x;
    const int sub = tid >> 7, i = tid & 127;
    const int t0f = c*LC + sub*LF;
    const float*  __restrict__ kp = g_k + (b*NS + t0f)*ND + i;
    const float*  __restrict__ vp = g_v + (b*NS + t0f)*ND + i;
    const float*  __restrict__ qp = g_q + (b*NS + t0f)*ND + i;
    const float4* __restrict__ gp = g_g4 + b*NS + t0f;

    // ---- A0: compose fine diag map over LF=16 steps (UG=4 prefetch) ----
    {
        float m00=1.f, m01=0.f, m10=0.f, m11=1.f, w0=0.f, w1=0.f;
        float kA[4], vA[4], kB[4], vB[4];
        float4 gA[4], gB[4];
        #pragma unroll
        for (int s = 0; s < 4; s++) { kA[s]=kp[s*ND]; vA[s]=vp[s*ND]; gA[s]=gp[s]; }
        #pragma unroll
        for (int g = 0; g < 4; g++) {
            const bool useA = ((g & 1) == 0);
            if (g < 3) {
                #pragma unroll
                for (int s = 0; s < 4; s++) {
                    int off = ((g+1)*4 + s)*ND, go = (g+1)*4 + s;
                    if (useA) { kB[s]=kp[off]; vB[s]=vp[off]; gB[s]=gp[go]; }
                    else      { kA[s]=kp[off]; vA[s]=vp[off]; gA[s]=gp[go]; }
                }
            }
            #pragma unroll
            for (int s = 0; s < 4; s++) {
                float  kk = useA ? kA[s] : kB[s];
                float  vv = useA ? vA[s] : vB[s];
                float4 gg = useA ? gA[s] : gB[s];
                float om = gg.x, e = gg.y, th = gg.z;
                float t1 = th*kk, c2 = t1*vv, d0 = -t1*kk, a00 = om + d0;
                float te0 = e*m10, te1 = e*m11;
                float n00 = fmaf(a00, m00, te0), n10 = fmaf(d0, m00, te0);
                float n01 = fmaf(a00, m01, te1), n11 = fmaf(d0, m01, te1);
                float tev = fmaf(e, w1, c2);
                float nw0 = fmaf(a00, w0, tev), nw1 = fmaf(d0, w0, tev);
                m00=n00; m01=n01; m10=n10; m11=n11; w0=nw0; w1=nw1;
            }
        }
        fm[(0*4+sub)*128+i] = m00; fm[(1*4+sub)*128+i] = m01;
        fm[(2*4+sub)*128+i] = m10; fm[(3*4+sub)*128+i] = m11;
        fm[(4*4+sub)*128+i] = w0;  fm[(5*4+sub)*128+i] = w1;
    }
    if (i == 0) {
        // fine weight map for this sub-chunk
        float ph = 1.f, qh = 1.f, gh = 0.f;
        #pragma unroll
        for (int s = LF-1; s >= 0; s--) {
            float4 g = gp[s];
            gh = fmaf(g.y, gh, g.x*ph);
            ph *= g.x;
            qh *= g.y;
        }
        wfm[sub*3+0] = ph; wfm[sub*3+1] = qh; wfm[sub*3+2] = gh;
    }
    __syncthreads();

    // ---- combine: sub-chunk entry state for diag ----
    const int ii = (b*NC + c)*ND + i;
    float dm = g_dinit0[ii], ds = g_dinit1[ii];
    for (int t = 0; t < sub; t++) {
        float a00 = fm[(0*4+t)*128+i], a01 = fm[(1*4+t)*128+i];
        float a10 = fm[(2*4+t)*128+i], a11 = fm[(3*4+t)*128+i];
        float v0  = fm[(4*4+t)*128+i], v1  = fm[(5*4+t)*128+i];
        float n0 = fmaf(a00, dm, fmaf(a01, ds, v0));
        float n1 = fmaf(a10, dm, fmaf(a11, ds, v1));
        dm = n0; ds = n1;
    }

    if (i == 0) {
        // weight entry for this sub-chunk + backward scan
        const int u = b*NC + c;
        float P = g_winit[u*3+0], E = g_winit[u*3+1], w = g_winit[u*3+2];
        for (int t = 3; t > sub; t--) {
            float ph = wfm[t*3+0], qh = wfm[t*3+1], gh = wfm[t*3+2];
            w = fmaf(qh, w, gh*P); P *= ph; E *= qh;
        }
        #pragma unroll
        for (int s = LF-1; s >= 0; s--) {
            float4 g = gp[s];
            float th = g.z;
            sA[sub*LF + s] = -th * w;
            sB[sub*LF + s] = -th * E;
            P *= g.x;
            E *= g.y;
            w  = fmaf(g.y, w, P);
        }
    }

    // ---- A1: replay LF=16 steps (UG=4 prefetch) ----
    {
        float* __restrict__ op = d_out + (b*NS + t0f)*ND + i;
        float kA[4], vA[4], qA[4], kB[4], vB[4], qB[4];
        float4 gA[4], gB[4];
        #pragma unroll
        for (int s = 0; s < 4; s++) { kA[s]=kp[s*ND]; vA[s]=vp[s*ND]; qA[s]=qp[s*ND]; gA[s]=gp[s]; }
        #pragma unroll
        for (int g = 0; g < 4; g++) {
            const bool useA = ((g & 1) == 0);
            if (g < 3) {
                #pragma unroll
                for (int s = 0; s < 4; s++) {
                    int off = ((g+1)*4 + s)*ND, go = (g+1)*4 + s;
                    if (useA) { kB[s]=kp[off]; vB[s]=vp[off]; qB[s]=qp[off]; gB[s]=gp[go]; }
                    else      { kA[s]=kp[off]; vA[s]=vp[off]; qA[s]=qp[off]; gA[s]=gp[go]; }
                }
            }
            #pragma unroll
            for (int s = 0; s < 4; s++) {
                float  kk = useA ? kA[s] : kB[s];
                float  vv = useA ? vA[s] : vB[s];
                float  qq = useA ? qA[s] : qB[s];
                float4 gg = useA ? gA[s] : gB[s];
                float om = gg.x, e = gg.y, th = gg.z;
                const int st = g*4 + s;
                op[st*ND] = qq * dm;
                float err = fmaf(kk, dm, -vv);
                const int row = sub*LF + st;
                Kraw[row*ND + i] = kk;
                Eraw[row*ND + i] = err;
                float t1 = th*kk, c2 = t1*vv, d0 = -t1*kk;
                float inner = fmaf(e, ds, c2);
                ds = fmaf(d0, dm, inner);
                dm = fmaf(om, dm, ds);
            }
        }
    }
    __syncthreads();

    // ---- phase B: convert + weight + transpose ----
    #pragma unroll
    for (int r = 0; r < 16; r++) {
        const int idx = tid + r*512;        // = s*ND + i2
        const int s = idx >> 7, i2 = idx & 127;
        const float kf = Kraw[idx];
        const float ef = Eraw[idx];
        const float pa = sA[s] * kf;
        const float pb = sB[s] * kf;
        __nv_bfloat16 h, l;
        bf16split(pa, h, l); KAh[i2*KP + s] = h; KAl[i2*KP + s] = l;
        bf16split(pb, h, l); KBh[i2*KP + s] = h; KBl[i2*KP + s] = l;
        bf16split(ef, h, l); ETh[i2*KP + s] = h; ETl[i2*KP + s] = l;
    }
    __syncthreads();

    // ---- phase C: tensor-core weighted outer products ----
    const int which = tid >> 8;
    const int t256 = tid & 255;
    const int lane = t256 & 31, warp = t256 >> 5;
    const int g = lane >> 2, tig = lane & 3;
    const int wm = warp >> 1, wn = warp & 1;
    const __nv_bfloat16* __restrict__ Ah = which ? KBh : KAh;
    const __nv_bfloat16* __restrict__ Al = which ? KBl : KAl;

    float acc[2][8][4];
    #pragma unroll
    for (int mt = 0; mt < 2; mt++)
        #pragma unroll
        for (int nt = 0; nt < 8; nt++)
            #pragma unroll
            for (int r = 0; r < 4; r++) acc[mt][nt][r] = 0.f;

    #pragma unroll
    for (int kk = 0; kk < LC; kk += 16) {
        unsigned ah[2][4], al[2][4];
        #pragma unroll
        for (int mt = 0; mt < 2; mt++) {
            const int r0 = (wm*32 + mt*16 + g)*KP + kk + tig*2;
            const int r1 = r0 + 8*KP;
            ah[mt][0] = *reinterpret_cast<const unsigned*>(&Ah[r0]);
            ah[mt][1] = *reinterpret_cast<const unsigned*>(&Ah[r1]);
            ah[mt][2] = *reinterpret_cast<const unsigned*>(&Ah[r0 + 8]);
            ah[mt][3] = *reinterpret_cast<const unsigned*>(&Ah[r1 + 8]);
            al[mt][0] = *reinterpret_cast<const unsigned*>(&Al[r0]);
            al[mt][1] = *reinterpret_cast<const unsigned*>(&Al[r1]);
            al[mt][2] = *reinterpret_cast<const unsigned*>(&Al[r0 + 8]);
            al[mt][3] = *reinterpret_cast<const unsigned*>(&Al[r1 + 8]);
        }
        #pragma unroll
        for (int nt = 0; nt < 8; nt++) {
            const int bo = (wn*64 + nt*8 + g)*KP + kk + tig*2;
            unsigned bh[2], bl[2];
            bh[0] = *reinterpret_cast<const unsigned*>(&ETh[bo]);
            bh[1] = *reinterpret_cast<const unsigned*>(&ETh[bo + 8]);
            bl[0] = *reinterpret_cast<const unsigned*>(&ETl[bo]);
            bl[1] = *reinterpret_cast<const unsigned*>(&ETl[bo + 8]);
            #pragma unroll
            for (int mt = 0; mt < 2; mt++) {
                mma16816(acc[mt][nt], ah[mt], bh);
                mma16816(acc[mt][nt], ah[mt], bl);
                mma16816(acc[mt][nt], al[mt], bh);
            }
        }
    }

    float* __restrict__ C = g_part + ((b*2 + which)*NC + c)*ND*ND;
    #pragma unroll
    for (int mt = 0; mt < 2; mt++) {
        const int r0 = wm*32 + mt*16 + g;
        const int r1 = r0 + 8;
        #pragma unroll
        for (int nt = 0; nt < 8; nt++) {
            const int c0 = wn*64 + nt*8 + tig*2;
            *reinterpret_cast<float2*>(&C[r0*ND + c0]) = make_float2(acc[mt][nt][0], acc[mt][nt][1]);
            *reinterpret_cast<float2*>(&C[r1*ND + c0]) = make_float2(acc[mt][nt][2], acc[mt][nt][3]);
        }
    }
}

// ============================================================
// Kernel 5: reduce split partials -> d_out tail (float4)
// ============================================================
__global__ __launch_bounds__(256) void reduce_kernel(float* __restrict__ d_out)
{
    const int g4 = blockIdx.x * 256 + threadIdx.x;   // [0, 65536) float4 units
    const int gid = g4 * 4;
    const int which = gid >> 17;
    const int r  = gid & 131071;
    const int b  = r >> 14;
    const int ij = r & 16383;
    const float* __restrict__ p = g_part + ((b*2 + which)*NC)*ND*ND + ij;
    float4 s = make_float4(0.f, 0.f, 0.f, 0.f);
    #pragma unroll
    for (int sp = 0; sp < NC; sp++) {
        float4 v = *reinterpret_cast<const float4*>(&p[sp*ND*ND]);
        s.x += v.x; s.y += v.y; s.z += v.z; s.w += v.w;
    }
    *reinterpret_cast<float4*>(&d_out[BSD + gid]) = s;
}

// ============================================================
extern "C" void kernel_launch(void* const* d_in, const int* in_sizes, int n_in,
                              void* d_out, int out_size)
{
    const float* x  = (const float*)d_in[0];
    const float* Wk = (const float*)d_in[1];
    const float* Wv = (const float*)d_in[2];
    const float* Wq = (const float*)d_in[3];
    const float* Wg = (const float*)d_in[4];
    const float* bg = (const float*)d_in[5];
    float* out = (float*)d_out;

    const int k1_smem = 4 * 128 * KP * (int)sizeof(__nv_bfloat16);  // 73728 B
    const int fused_smem = (2*LC*ND + 6*4*128 + 2*LC + 16) * (int)sizeof(float)
                         + 6*ND*KP*(int)sizeof(__nv_bfloat16);      // ~188 KB
    cudaFuncSetAttribute(k1_qkv_gates, cudaFuncAttributeMaxDynamicSharedMemorySize, k1_smem);
    cudaFuncSetAttribute(fused3_kernel, cudaFuncAttributeMaxDynamicSharedMemorySize, fused_smem);

    k1_qkv_gates<<<dim3(64, 4), 256, k1_smem>>>(x, Wk, Wv, Wq, Wg, bg);
    pass1_kernel<<<NB*NC + 1, 128>>>();
    pass2_kernel<<<NB + 1, 128>>>();
    fused3_kernel<<<NB*NC, 512, fused_smem>>>(out);
    reduce_kernel<<<256, 256>>>(out);
}

// round 8
// speedup vs baseline: 5.8987x; 1.0303x over previous
#include <cuda_runtime.h>
#include <cuda_bf16.h>

#define NB 8
#define NS 1024
#define ND 128
#define NROWS (NB*NS)   // 8192
#define BSD (NB*NS*ND)  // 1048576

#define NC 16           // coarse chunks (GEMM splits)
#define LC 64           // steps per coarse chunk
#define LF 16           // steps per fine sub-chunk (replay granularity)
#define UG 8            // prefetch group size (pass1)
#define NGRP (LC/UG)

#define KP 72           // padded bf16 k-stride in smem (conflict-free frag loads)

// ---- scratch (static device globals; no runtime allocation) ----
__device__ float  g_k[NROWS*ND];
__device__ float  g_v[NROWS*ND];
__device__ float  g_q[NROWS*ND];
__device__ float4 g_g4[NROWS];           // (om=1-a, e, th, 0) per (b,t)
__device__ float  g_dmap[6*NB*NC*ND];    // composed coarse diag maps
__device__ float  g_wmap[3*NB*NC];
__device__ float  g_part[NB*2*NC*ND*ND];

// ---- mma.sync m16n8k16 bf16 -> f32 ----
__device__ __forceinline__ void mma16816(float* c, const unsigned* a, const unsigned* b)
{
    asm volatile(
        "mma.sync.aligned.m16n8k16.row.col.f32.bf16.bf16.f32 "
        "{%0,%1,%2,%3}, {%4,%5,%6,%7}, {%8,%9}, {%0,%1,%2,%3};"
        : "+f"(c[0]), "+f"(c[1]), "+f"(c[2]), "+f"(c[3])
        : "r"(a[0]), "r"(a[1]), "r"(a[2]), "r"(a[3]), "r"(b[0]), "r"(b[1]));
}

__device__ __forceinline__ void bf16split(float f, __nv_bfloat16& h, __nv_bfloat16& l)
{
    h = __float2bfloat16_rn(f);
    l = __float2bfloat16_rn(f - __bfloat162float(h));
}

// ============================================================
// Kernel 1: y<3: k/v/q = x@W via bf16-split tensor mma; y==3: gates
// ============================================================
__global__ __launch_bounds__(256) void k1_qkv_gates(
    const float* __restrict__ x, const float* __restrict__ Wk,
    const float* __restrict__ Wv, const float* __restrict__ Wq,
    const float* __restrict__ Wg, const float* __restrict__ bg)
{
    const int which = blockIdx.y;
    if (which == 3) {
        const int base = blockIdx.x * 128;
        const int w = threadIdx.x >> 5, lane = threadIdx.x & 31;
        const float b0 = bg[0], b1 = bg[1], b2 = bg[2];
        const float w0a = Wg[lane*3+0],      w0b = Wg[lane*3+1],      w0c = Wg[lane*3+2];
        const float w1a = Wg[(lane+32)*3+0], w1b = Wg[(lane+32)*3+1], w1c = Wg[(lane+32)*3+2];
        const float w2a = Wg[(lane+64)*3+0], w2b = Wg[(lane+64)*3+1], w2c = Wg[(lane+64)*3+2];
        const float w3a = Wg[(lane+96)*3+0], w3b = Wg[(lane+96)*3+1], w3c = Wg[(lane+96)*3+2];
        for (int rr = 0; rr < 16; rr++) {
            const int r = base + w*16 + rr;
            const float* __restrict__ xr = x + r * ND;
            float x0 = xr[lane], x1 = xr[lane+32], x2 = xr[lane+64], x3 = xr[lane+96];
            float s0 = x0*w0a + x1*w1a + x2*w2a + x3*w3a;
            float s1 = x0*w0b + x1*w1b + x2*w2b + x3*w3b;
            float s2 = x0*w0c + x1*w1c + x2*w2c + x3*w3c;
            #pragma unroll
            for (int o = 16; o; o >>= 1) {
                s0 += __shfl_xor_sync(0xffffffffu, s0, o);
                s1 += __shfl_xor_sync(0xffffffffu, s1, o);
                s2 += __shfl_xor_sync(0xffffffffu, s2, o);
            }
            if (lane == 0) {
                float om = 1.f / (1.f + expf(s0 + b0));       // 1 - sigmoid
                float e  = 1.f / (1.f + expf(-(s1 + b1)));
                float th = 1.f / (1.f + expf(-(s2 + b2)));
                g_g4[r] = make_float4(om, e, th, 0.f);
            }
        }
        return;
    }
    extern __shared__ __nv_bfloat16 bsm[];
    __nv_bfloat16* __restrict__ XH  = bsm;
    __nv_bfloat16* __restrict__ XL  = XH  + 128*KP;
    __nv_bfloat16* __restrict__ WTH = XL  + 128*KP;
    __nv_bfloat16* __restrict__ WTL = WTH + 128*KP;

    const float* __restrict__ W = (which == 0) ? Wk : ((which == 1) ? Wv : Wq);
    float* __restrict__ out = (which == 0) ? g_k : ((which == 1) ? g_v : g_q);
    const int rowBase = blockIdx.x * 128;

    const int tid  = threadIdx.x;
    const int lane = tid & 31;
    const int warp = tid >> 5;
    const int g    = lane >> 2;
    const int tig  = lane & 3;
    const int wm   = warp >> 1;
    const int wn   = warp & 1;

    float acc[2][8][4];
    #pragma unroll
    for (int mt = 0; mt < 2; mt++)
        #pragma unroll
        for (int nt = 0; nt < 8; nt++)
            #pragma unroll
            for (int r = 0; r < 4; r++) acc[mt][nt][r] = 0.f;

    for (int k0 = 0; k0 < 128; k0 += 64) {
        {
            const int row = tid >> 1, half = tid & 1;
            const float* __restrict__ src = x + (rowBase + row)*ND + k0 + half*32;
            __nv_bfloat16* __restrict__ dh = XH + row*KP + half*32;
            __nv_bfloat16* __restrict__ dl = XL + row*KP + half*32;
            #pragma unroll
            for (int j = 0; j < 8; j++) {
                float4 v = *reinterpret_cast<const float4*>(&src[j*4]);
                #pragma unroll
                for (int i = 0; i < 4; i++) {
                    __nv_bfloat16 h, l;
                    bf16split((&v.x)[i], h, l);
                    dh[j*4+i] = h; dl[j*4+i] = l;
                }
            }
        }
        {
            const int krow = tid >> 2, nb = (tid & 3)*32;
            const float* __restrict__ src = W + (k0 + krow)*ND + nb;
            #pragma unroll
            for (int j = 0; j < 8; j++) {
                float4 v = *reinterpret_cast<const float4*>(&src[j*4]);
                #pragma unroll
                for (int i = 0; i < 4; i++) {
                    __nv_bfloat16 h, l;
                    bf16split((&v.x)[i], h, l);
                    const int n = nb + j*4 + i;
                    WTH[n*KP + krow] = h;
                    WTL[n*KP + krow] = l;
                }
            }
        }
        __syncthreads();

        #pragma unroll
        for (int kk = 0; kk < 64; kk += 16) {
            unsigned ah[2][4], al[2][4];
            #pragma unroll
            for (int mt = 0; mt < 2; mt++) {
                const int r0 = (wm*32 + mt*16 + g)*KP + kk + tig*2;
                const int r1 = r0 + 8*KP;
                ah[mt][0] = *reinterpret_cast<const unsigned*>(&XH[r0]);
                ah[mt][1] = *reinterpret_cast<const unsigned*>(&XH[r1]);
                ah[mt][2] = *reinterpret_cast<const unsigned*>(&XH[r0 + 8]);
                ah[mt][3] = *reinterpret_cast<const unsigned*>(&XH[r1 + 8]);
                al[mt][0] = *reinterpret_cast<const unsigned*>(&XL[r0]);
                al[mt][1] = *reinterpret_cast<const unsigned*>(&XL[r1]);
                al[mt][2] = *reinterpret_cast<const unsigned*>(&XL[r0 + 8]);
                al[mt][3] = *reinterpret_cast<const unsigned*>(&XL[r1 + 8]);
            }
            #pragma unroll
            for (int nt = 0; nt < 8; nt++) {
                const int bo = (wn*64 + nt*8 + g)*KP + kk + tig*2;
                unsigned bh[2], bl[2];
                bh[0] = *reinterpret_cast<const unsigned*>(&WTH[bo]);
                bh[1] = *reinterpret_cast<const unsigned*>(&WTH[bo + 8]);
                bl[0] = *reinterpret_cast<const unsigned*>(&WTL[bo]);
                bl[1] = *reinterpret_cast<const unsigned*>(&WTL[bo + 8]);
                #pragma unroll
                for (int mt = 0; mt < 2; mt++) {
                    mma16816(acc[mt][nt], ah[mt], bh);
                    mma16816(acc[mt][nt], ah[mt], bl);
                    mma16816(acc[mt][nt], al[mt], bh);
                }
            }
        }
        __syncthreads();
    }

    #pragma unroll
    for (int mt = 0; mt < 2; mt++) {
        const int r0 = rowBase + wm*32 + mt*16 + g;
        const int r1 = r0 + 8;
        #pragma unroll
        for (int nt = 0; nt < 8; nt++) {
            const int c0 = wn*64 + nt*8 + tig*2;
            *reinterpret_cast<float2*>(&out[r0*ND + c0]) = make_float2(acc[mt][nt][0], acc[mt][nt][1]);
            *reinterpret_cast<float2*>(&out[r1*ND + c0]) = make_float2(acc[mt][nt][2], acc[mt][nt][3]);
        }
    }
}

// ============================================================
// Pass 1: coarse chunk map composition (diag maps + weight maps)
// ============================================================
__global__ __launch_bounds__(128) void pass1_kernel()
{
    const int blk = blockIdx.x;
    if (blk < NB*NC) {
        const int b = blk >> 4, c = blk & (NC-1);
        const int i = threadIdx.x;
        const int t0 = c * LC;
        const float*  __restrict__ kp = g_k + (b*NS + t0)*ND + i;
        const float*  __restrict__ vp = g_v + (b*NS + t0)*ND + i;
        const float4* __restrict__ gp = g_g4 + b*NS + t0;

        float m00=1.f, m01=0.f, m10=0.f, m11=1.f, w0=0.f, w1=0.f;
        float kA[UG], vA[UG], kB[UG], vB[UG];
        float4 gA[UG], gB[UG];
        #pragma unroll
        for (int s = 0; s < UG; s++) { kA[s]=kp[s*ND]; vA[s]=vp[s*ND]; gA[s]=gp[s]; }

        #pragma unroll
        for (int g = 0; g < NGRP; g++) {
            const bool useA = ((g & 1) == 0);
            if (g + 1 < NGRP) {
                #pragma unroll
                for (int s = 0; s < UG; s++) {
                    int off = ((g+1)*UG + s)*ND;
                    int go  = (g+1)*UG + s;
                    if (useA) { kB[s]=kp[off]; vB[s]=vp[off]; gB[s]=gp[go]; }
                    else      { kA[s]=kp[off]; vA[s]=vp[off]; gA[s]=gp[go]; }
                }
            }
            #pragma unroll
            for (int s = 0; s < UG; s++) {
                float  kk = useA ? kA[s] : kB[s];
                float  vv = useA ? vA[s] : vB[s];
                float4 gg = useA ? gA[s] : gB[s];
                float om = gg.x, e = gg.y, th = gg.z;
                float t1 = th*kk, c2 = t1*vv, d0 = -t1*kk, a00 = om + d0;
                float te0 = e*m10, te1 = e*m11;
                float n00 = fmaf(a00, m00, te0), n10 = fmaf(d0, m00, te0);
                float n01 = fmaf(a00, m01, te1), n11 = fmaf(d0, m01, te1);
                float tev = fmaf(e, w1, c2);
                float nw0 = fmaf(a00, w0, tev), nw1 = fmaf(d0, w0, tev);
                m00=n00; m01=n01; m10=n10; m11=n11; w0=nw0; w1=nw1;
            }
        }
        const int base = (b*NC + c)*ND + i;
        const int ST = NB*NC*ND;
        g_dmap[0*ST+base] = m00; g_dmap[1*ST+base] = m01;
        g_dmap[2*ST+base] = m10; g_dmap[3*ST+base] = m11;
        g_dmap[4*ST+base] = w0;  g_dmap[5*ST+base] = w1;
    } else {
        const int u = threadIdx.x;
        const int b = u >> 4, wc = u & (NC-1);
        const float4* __restrict__ gp = g_g4 + b*NS + wc*LC;
        float ph = 1.f, qh = 1.f, gh = 0.f;
        #pragma unroll 4
        for (int s = LC-1; s >= 0; s--) {
            float4 g = gp[s];
            float p = g.x, q = g.y;
            gh = fmaf(q, gh, p*ph);
            ph *= p;
            qh *= q;
        }
        g_wmap[0*NB*NC + u] = ph;
        g_wmap[1*NB*NC + u] = qh;
        g_wmap[2*NB*NC + u] = gh;
    }
}

// ============================================================
// Fused pass 3 (pass2 inlined): per (b, coarse chunk) block, 512 threads
//  prefetch: coarse diag maps t<c -> ENT (smem), weight maps -> wENT
//  A0: thread (sub,i) composes 16-step fine diag map -> fm; stages k->Kraw,
//      v->Eraw, gates->sG; i==0 threads compose fine weight maps -> wfm
//  combine: coarse entry (ENT serial) + fine maps (fm) -> per-thread state;
//      i==0: coarse weight entry (wENT) + fine (wfm) + 16-step scan -> sA/sB
//  A1: replay 16 steps from smem (q from global regs), y -> d_out, err -> Eraw
//  B:  convert+weight+transpose to bf16 hi/lo [i][s] (overlays ENT/fm)
//  C:  warps 0-7 A-weighted (M) partial, warps 8-15 B-weighted (S) via mma
// ============================================================
#define F3_ENT_OFF   65536
#define F3_FM_OFF    (65536 + 49152)
#define F3_SG_OFF    176128
#define F3_SA_OFF    177152
#define F3_WENT_OFF  177664
#define F3_SMEM      177920

__global__ __launch_bounds__(512) void fused3_kernel(float* __restrict__ d_out)
{
    extern __shared__ char smc[];
    float* __restrict__ Kraw = reinterpret_cast<float*>(smc);            // [64][128]
    float* __restrict__ Eraw = Kraw + LC*ND;                             // [64][128]
    float* __restrict__ ENT  = reinterpret_cast<float*>(smc + F3_ENT_OFF);  // [6][16][128]
    float* __restrict__ fm   = reinterpret_cast<float*>(smc + F3_FM_OFF);   // [6][4][128]
    float4* __restrict__ sG  = reinterpret_cast<float4*>(smc + F3_SG_OFF);  // [64]
    float* __restrict__ sA   = reinterpret_cast<float*>(smc + F3_SA_OFF);   // [64]
    float* __restrict__ sB   = sA + LC;                                  // [64]
    float* __restrict__ wENT = reinterpret_cast<float*>(smc + F3_WENT_OFF); // [16][3]
    float* __restrict__ wfm  = wENT + 48;                                // [4][3]
    __nv_bfloat16* __restrict__ KAh = reinterpret_cast<__nv_bfloat16*>(smc + F3_ENT_OFF);
    __nv_bfloat16* __restrict__ KAl = KAh + ND*KP;
    __nv_bfloat16* __restrict__ KBh = KAl + ND*KP;
    __nv_bfloat16* __restrict__ KBl = KBh + ND*KP;
    __nv_bfloat16* __restrict__ ETh = KBl + ND*KP;
    __nv_bfloat16* __restrict__ ETl = ETh + ND*KP;

    const int b = blockIdx.x >> 4, c = blockIdx.x & (NC-1);
    const int tid = threadIdx.x;
    const int sub = tid >> 7, i = tid & 127;
    const int t0f = c*LC + sub*LF;
    const float*  __restrict__ kp = g_k + (b*NS + t0f)*ND + i;
    const float*  __restrict__ vp = g_v + (b*NS + t0f)*ND + i;
    const float*  __restrict__ qp = g_q + (b*NS + t0f)*ND + i;
    const float4* __restrict__ gp = g_g4 + b*NS + t0f;

    // ---- cooperative prefetch of coarse maps (entry-state inputs) ----
    {
        const int ST = NB*NC*ND;
        const int nEl = c * 128;
        #pragma unroll
        for (int jj = 0; jj < 6; jj++)
            for (int u = tid; u < nEl; u += 512)
                ENT[jj*2048 + u] = g_dmap[jj*ST + b*NC*ND + u];
        if (tid < 48) {
            const int t = tid / 3, j = tid % 3;
            wENT[t*3 + j] = g_wmap[j*NB*NC + b*NC + t];
        }
    }
    // gates -> smem (per sub, 16 threads)
    if (i < LF) sG[sub*LF + i] = gp[i];

    // ---- A0: compose fine diag map over LF=16 steps; stage k/v to smem ----
    {
        float m00=1.f, m01=0.f, m10=0.f, m11=1.f, w0=0.f, w1=0.f;
        float kA[4], vA[4], kB[4], vB[4];
        float4 gA[4], gB[4];
        #pragma unroll
        for (int s = 0; s < 4; s++) { kA[s]=kp[s*ND]; vA[s]=vp[s*ND]; gA[s]=gp[s]; }
        #pragma unroll
        for (int g = 0; g < 4; g++) {
            const bool useA = ((g & 1) == 0);
            if (g < 3) {
                #pragma unroll
                for (int s = 0; s < 4; s++) {
                    int off = ((g+1)*4 + s)*ND, go = (g+1)*4 + s;
                    if (useA) { kB[s]=kp[off]; vB[s]=vp[off]; gB[s]=gp[go]; }
                    else      { kA[s]=kp[off]; vA[s]=vp[off]; gA[s]=gp[go]; }
                }
            }
            #pragma unroll
            for (int s = 0; s < 4; s++) {
                float  kk = useA ? kA[s] : kB[s];
                float  vv = useA ? vA[s] : vB[s];
                float4 gg = useA ? gA[s] : gB[s];
                const int row = sub*LF + g*4 + s;
                Kraw[row*ND + i] = kk;
                Eraw[row*ND + i] = vv;
                float om = gg.x, e = gg.y, th = gg.z;
                float t1 = th*kk, c2 = t1*vv, d0 = -t1*kk, a00 = om + d0;
                float te0 = e*m10, te1 = e*m11;
                float n00 = fmaf(a00, m00, te0), n10 = fmaf(d0, m00, te0);
                float n01 = fmaf(a00, m01, te1), n11 = fmaf(d0, m01, te1);
                float tev = fmaf(e, w1, c2);
                float nw0 = fmaf(a00, w0, tev), nw1 = fmaf(d0, w0, tev);
                m00=n00; m01=n01; m10=n10; m11=n11; w0=nw0; w1=nw1;
            }
        }
        fm[(0*4+sub)*128+i] = m00; fm[(1*4+sub)*128+i] = m01;
        fm[(2*4+sub)*128+i] = m10; fm[(3*4+sub)*128+i] = m11;
        fm[(4*4+sub)*128+i] = w0;  fm[(5*4+sub)*128+i] = w1;
    }
    if (i == 0) {
        // fine weight map for this sub-chunk
        float ph = 1.f, qh = 1.f, gh = 0.f;
        #pragma unroll
        for (int s = LF-1; s >= 0; s--) {
            float4 g = gp[s];
            gh = fmaf(g.y, gh, g.x*ph);
            ph *= g.x;
            qh *= g.y;
        }
        wfm[sub*3+0] = ph; wfm[sub*3+1] = qh; wfm[sub*3+2] = gh;
    }
    __syncthreads();

    // ---- combine: coarse entry (over chunks t<c) then fine maps (t<sub) ----
    float dm = 0.f, ds = 0.f;
    for (int t = 0; t < c; t++) {
        float a00 = ENT[0*2048 + t*128 + i], a01 = ENT[1*2048 + t*128 + i];
        float a10 = ENT[2*2048 + t*128 + i], a11 = ENT[3*2048 + t*128 + i];
        float v0  = ENT[4*2048 + t*128 + i], v1  = ENT[5*2048 + t*128 + i];
        float n0 = fmaf(a00, dm, fmaf(a01, ds, v0));
        float n1 = fmaf(a10, dm, fmaf(a11, ds, v1));
        dm = n0; ds = n1;
    }
    for (int t = 0; t < sub; t++) {
        float a00 = fm[(0*4+t)*128+i], a01 = fm[(1*4+t)*128+i];
        float a10 = fm[(2*4+t)*128+i], a11 = fm[(3*4+t)*128+i];
        float v0  = fm[(4*4+t)*128+i], v1  = fm[(5*4+t)*128+i];
        float n0 = fmaf(a00, dm, fmaf(a01, ds, v0));
        float n1 = fmaf(a10, dm, fmaf(a11, ds, v1));
        dm = n0; ds = n1;
    }

    if (i == 0) {
        // coarse weight entry (chunks t>c) then fine (t>sub), then 16-step scan
        float P = 1.f, E = 1.f, w = 1.f;
        for (int t = NC-1; t > c; t--) {
            float ph = wENT[t*3+0], qh = wENT[t*3+1], gh = wENT[t*3+2];
            float nw = fmaf(qh, w, gh*P);
            P *= ph; E *= qh; w = nw;
        }
        for (int t = 3; t > sub; t--) {
            float ph = wfm[t*3+0], qh = wfm[t*3+1], gh = wfm[t*3+2];
            float nw = fmaf(qh, w, gh*P);
            P *= ph; E *= qh; w = nw;
        }
        #pragma unroll
        for (int s = LF-1; s >= 0; s--) {
            float4 g = sG[sub*LF + s];
            float th = g.z;
            sA[sub*LF + s] = -th * w;
            sB[sub*LF + s] = -th * E;
            P *= g.x;
            E *= g.y;
            w  = fmaf(g.y, w, P);
        }
    }

    // ---- A1: replay LF=16 steps from smem (q prefetched to regs) ----
    {
        float* __restrict__ op = d_out + (b*NS + t0f)*ND + i;
        float q16[LF];
        #pragma unroll
        for (int s = 0; s < LF; s++) q16[s] = qp[s*ND];
        #pragma unroll
        for (int st = 0; st < LF; st++) {
            const int row = sub*LF + st;
            float4 gg = sG[row];
            float  kk = Kraw[row*ND + i];
            float  vv = Eraw[row*ND + i];
            float om = gg.x, e = gg.y, th = gg.z;
            op[st*ND] = q16[st] * dm;
            float err = fmaf(kk, dm, -vv);
            Eraw[row*ND + i] = err;
            float t1 = th*kk, c2 = t1*vv, d0 = -t1*kk;
            float inner = fmaf(e, ds, c2);
            ds = fmaf(d0, dm, inner);
            dm = fmaf(om, dm, ds);
        }
    }
    __syncthreads();

    // ---- phase B: convert + weight + transpose (overlays ENT/fm) ----
    #pragma unroll
    for (int r = 0; r < 16; r++) {
        const int idx = tid + r*512;        // = s*ND + i2
        const int s = idx >> 7, i2 = idx & 127;
        const float kf = Kraw[idx];
        const float ef = Eraw[idx];
        const float pa = sA[s] * kf;
        const float pb = sB[s] * kf;
        __nv_bfloat16 h, l;
        bf16split(pa, h, l); KAh[i2*KP + s] = h; KAl[i2*KP + s] = l;
        bf16split(pb, h, l); KBh[i2*KP + s] = h; KBl[i2*KP + s] = l;
        bf16split(ef, h, l); ETh[i2*KP + s] = h; ETl[i2*KP + s] = l;
    }
    __syncthreads();

    // ---- phase C: tensor-core weighted outer products ----
    const int which = tid >> 8;
    const int t256 = tid & 255;
    const int lane = t256 & 31, warp = t256 >> 5;
    const int g = lane >> 2, tig = lane & 3;
    const int wm = warp >> 1, wn = warp & 1;
    const __nv_bfloat16* __restrict__ Ah = which ? KBh : KAh;
    const __nv_bfloat16* __restrict__ Al = which ? KBl : KAl;

    float acc[2][8][4];
    #pragma unroll
    for (int mt = 0; mt < 2; mt++)
        #pragma unroll
        for (int nt = 0; nt < 8; nt++)
            #pragma unroll
            for (int r = 0; r < 4; r++) acc[mt][nt][r] = 0.f;

    #pragma unroll
    for (int kk = 0; kk < LC; kk += 16) {
        unsigned ah[2][4], al[2][4];
        #pragma unroll
        for (int mt = 0; mt < 2; mt++) {
            const int r0 = (wm*32 + mt*16 + g)*KP + kk + tig*2;
            const int r1 = r0 + 8*KP;
            ah[mt][0] = *reinterpret_cast<const unsigned*>(&Ah[r0]);
            ah[mt][1] = *reinterpret_cast<const unsigned*>(&Ah[r1]);
            ah[mt][2] = *reinterpret_cast<const unsigned*>(&Ah[r0 + 8]);
            ah[mt][3] = *reinterpret_cast<const unsigned*>(&Ah[r1 + 8]);
            al[mt][0] = *reinterpret_cast<const unsigned*>(&Al[r0]);
            al[mt][1] = *reinterpret_cast<const unsigned*>(&Al[r1]);
            al[mt][2] = *reinterpret_cast<const unsigned*>(&Al[r0 + 8]);
            al[mt][3] = *reinterpret_cast<const unsigned*>(&Al[r1 + 8]);
        }
        #pragma unroll
        for (int nt = 0; nt < 8; nt++) {
            const int bo = (wn*64 + nt*8 + g)*KP + kk + tig*2;
            unsigned bh[2], bl[2];
            bh[0] = *reinterpret_cast<const unsigned*>(&ETh[bo]);
            bh[1] = *reinterpret_cast<const unsigned*>(&ETh[bo + 8]);
            bl[0] = *reinterpret_cast<const unsigned*>(&ETl[bo]);
            bl[1] = *reinterpret_cast<const unsigned*>(&ETl[bo + 8]);
            #pragma unroll
            for (int mt = 0; mt < 2; mt++) {
                mma16816(acc[mt][nt], ah[mt], bh);
                mma16816(acc[mt][nt], ah[mt], bl);
                mma16816(acc[mt][nt], al[mt], bh);
            }
        }
    }

    float* __restrict__ C = g_part + ((b*2 + which)*NC + c)*ND*ND;
    #pragma unroll
    for (int mt = 0; mt < 2; mt++) {
        const int r0 = wm*32 + mt*16 + g;
        const int r1 = r0 + 8;
        #pragma unroll
        for (int nt = 0; nt < 8; nt++) {
            const int c0 = wn*64 + nt*8 + tig*2;
            *reinterpret_cast<float2*>(&C[r0*ND + c0]) = make_float2(acc[mt][nt][0], acc[mt][nt][1]);
            *reinterpret_cast<float2*>(&C[r1*ND + c0]) = make_float2(acc[mt][nt][2], acc[mt][nt][3]);
        }
    }
}

// ============================================================
// Kernel 5: reduce split partials -> d_out tail (float4)
// ============================================================
__global__ __launch_bounds__(256) void reduce_kernel(float* __restrict__ d_out)
{
    const int g4 = blockIdx.x * 256 + threadIdx.x;   // [0, 65536) float4 units
    const int gid = g4 * 4;
    const int which = gid >> 17;
    const int r  = gid & 131071;
    const int b  = r >> 14;
    const int ij = r & 16383;
    const float* __restrict__ p = g_part + ((b*2 + which)*NC)*ND*ND + ij;
    float4 s = make_float4(0.f, 0.f, 0.f, 0.f);
    #pragma unroll
    for (int sp = 0; sp < NC; sp++) {
        float4 v = *reinterpret_cast<const float4*>(&p[sp*ND*ND]);
        s.x += v.x; s.y += v.y; s.z += v.z; s.w += v.w;
    }
    *reinterpret_cast<float4*>(&d_out[BSD + gid]) = s;
}

// ============================================================
extern "C" void kernel_launch(void* const* d_in, const int* in_sizes, int n_in,
                              void* d_out, int out_size)
{
    const float* x  = (const float*)d_in[0];
    const float* Wk = (const float*)d_in[1];
    const float* Wv = (const float*)d_in[2];
    const float* Wq = (const float*)d_in[3];
    const float* Wg = (const float*)d_in[4];
    const float* bg = (const float*)d_in[5];
    float* out = (float*)d_out;

    const int k1_smem = 4 * 128 * KP * (int)sizeof(__nv_bfloat16);  // 73728 B
    cudaFuncSetAttribute(k1_qkv_gates, cudaFuncAttributeMaxDynamicSharedMemorySize, k1_smem);
    cudaFuncSetAttribute(fused3_kernel, cudaFuncAttributeMaxDynamicSharedMemorySize, F3_SMEM);

    k1_qkv_gates<<<dim3(64, 4), 256, k1_smem>>>(x, Wk, Wv, Wq, Wg, bg);
    pass1_kernel<<<NB*NC + 1, 128>>>();
    fused3_kernel<<<NB*NC, 512, F3_SMEM>>>(out);
    reduce_kernel<<<256, 256>>>(out);
}